// round 8
// baseline (speedup 1.0000x reference)
#include <cuda_runtime.h>
#include <cuda_fp16.h>
#include <math.h>

#define BATCH 4
#define SEQ   2048
#define DM    1024
#define NH    16
#define HD    64
#define NTOK  (BATCH * SEQ)   // 8192
#define LN_EPS 1e-6f

// ---------------------------------------------------------------------------
// Device-global scratch (no allocation allowed anywhere)
// ---------------------------------------------------------------------------
__device__ __half g_hx[NTOK * DM];            // x in fp16
__device__ __half g_hwq[DM * DM], g_hwk[DM * DM], g_hwv[DM * DM], g_hwo[DM * DM];
__device__ __half g_q[NTOK * DM];             // [B,H,S,HD] fp16 (pre-scaled by 1/8)
__device__ __half g_k[NTOK * DM];             // [B,H,S,HD]
__device__ __half g_v[NTOK * DM];             // [B,H,S,HD]
__device__ __half g_ah[NTOK * DM];            // attention out [B,S,DM] fp16
__device__ float  g_proj[NTOK * DM];          // O-projection out fp32

// ---------------------------------------------------------------------------
// PTX helpers
// ---------------------------------------------------------------------------
__device__ __forceinline__ unsigned smem_u32(const void* p) {
    return (unsigned)__cvta_generic_to_shared(p);
}
__device__ __forceinline__ void ldsm4(unsigned* r, unsigned a) {
    asm volatile("ldmatrix.sync.aligned.m8n8.x4.shared.b16 {%0,%1,%2,%3},[%4];"
                 : "=r"(r[0]), "=r"(r[1]), "=r"(r[2]), "=r"(r[3]) : "r"(a));
}
__device__ __forceinline__ void ldsm4t(unsigned* r, unsigned a) {
    asm volatile("ldmatrix.sync.aligned.m8n8.x4.trans.shared.b16 {%0,%1,%2,%3},[%4];"
                 : "=r"(r[0]), "=r"(r[1]), "=r"(r[2]), "=r"(r[3]) : "r"(a));
}
__device__ __forceinline__ void mma16816(float* c, const unsigned* a, const unsigned* b) {
    asm volatile(
        "mma.sync.aligned.m16n8k16.row.col.f32.f16.f16.f32 "
        "{%0,%1,%2,%3},{%4,%5,%6,%7},{%8,%9},{%0,%1,%2,%3};"
        : "+f"(c[0]), "+f"(c[1]), "+f"(c[2]), "+f"(c[3])
        : "r"(a[0]), "r"(a[1]), "r"(a[2]), "r"(a[3]), "r"(b[0]), "r"(b[1]));
}
__device__ __forceinline__ void cp16(unsigned dst, const void* src) {
    asm volatile("cp.async.cg.shared.global [%0],[%1],16;" :: "r"(dst), "l"(src));
}
#define CP_COMMIT() asm volatile("cp.async.commit_group;")
#define CP_WAIT1()  asm volatile("cp.async.wait_group 1;")
#define CP_WAIT0()  asm volatile("cp.async.wait_group 0;")

__device__ __forceinline__ unsigned pack2(float x, float y) {
    __half2 h = __floats2half2_rn(x, y);
    return *reinterpret_cast<unsigned*>(&h);
}

// ---------------------------------------------------------------------------
// fp32 -> fp16 conversion (x)
// ---------------------------------------------------------------------------
__global__ __launch_bounds__(256) void cvt_kernel(
    const float* __restrict__ in, __half* __restrict__ out, int n)
{
    int i = (blockIdx.x * 256 + threadIdx.x) * 4;
    if (i >= n) return;
    float4 v = *(const float4*)(in + i);
    *(unsigned*)(out + i)     = pack2(v.x, v.y);
    *(unsigned*)(out + i + 2) = pack2(v.z, v.w);
}

// All 4 weights in one launch (blockIdx.y selects the matrix)
__global__ __launch_bounds__(256) void cvt_w_kernel(
    const float* __restrict__ W0, const float* __restrict__ W1,
    const float* __restrict__ W2, const float* __restrict__ W3,
    __half* __restrict__ O0, __half* __restrict__ O1,
    __half* __restrict__ O2, __half* __restrict__ O3)
{
    const float* W; __half* O;
    switch (blockIdx.y) {
        case 0: W = W0; O = O0; break;
        case 1: W = W1; O = O1; break;
        case 2: W = W2; O = O2; break;
        default: W = W3; O = O3; break;
    }
    int i = (blockIdx.x * 256 + threadIdx.x) * 4;
    float4 v = *(const float4*)(W + i);
    *(unsigned*)(O + i)     = pack2(v.x, v.y);
    *(unsigned*)(O + i + 2) = pack2(v.z, v.w);
}

// ---------------------------------------------------------------------------
// fp16 tensor-core GEMM (proven R6 version): C = A @ W + bias
// BM=BN=128, BK=32, 256 thr (8 warps 2x4), warp tile 64x32, double-buffered.
// MODE 1: fp16 out, head-split [B,H,S,HD], scaled. MODE 0: fp32 row-major.
// ---------------------------------------------------------------------------
#define GBM 128
#define GBN 128
#define GBK 32
#define ASTR 40
#define BSTR 136
#define A_STAGE (GBM * ASTR)   // 5120 halfs
#define B_STAGE (GBK * BSTR)   // 4352 halfs

template <int MODE>
__global__ __launch_bounds__(256) void gemm_h(
    const __half* __restrict__ Ag, const __half* __restrict__ Wg,
    const float* __restrict__ bias, float scale,
    float* __restrict__ Cf, __half* __restrict__ Ch)
{
    __shared__ __half sA[2 * A_STAGE];
    __shared__ __half sB[2 * B_STAGE];

    const int tid = threadIdx.x;
    const int lane = tid & 31, warp = tid >> 5;
    const int wm = (warp >> 2) * 64;
    const int wn = (warp & 3) * 32;
    const int m0 = blockIdx.y * GBM;
    const int n0 = blockIdx.x * GBN;
    const unsigned sAb = smem_u32(sA), sBb = smem_u32(sB);

    float acc[4][4][4];
    #pragma unroll
    for (int i = 0; i < 4; i++)
        #pragma unroll
        for (int j = 0; j < 4; j++)
            #pragma unroll
            for (int r = 0; r < 4; r++) acc[i][j][r] = 0.0f;

    auto load_stage = [&](int st, int k0) {
        #pragma unroll
        for (int c = 0; c < 2; c++) {
            int id = tid + c * 256;
            int row = id >> 2, col = (id & 3) * 8;
            cp16(sAb + (st * A_STAGE + row * ASTR + col) * 2,
                 Ag + (size_t)(m0 + row) * DM + k0 + col);
        }
        #pragma unroll
        for (int c = 0; c < 2; c++) {
            int id = tid + c * 256;
            int row = id >> 4, col = (id & 15) * 8;
            cp16(sBb + (st * B_STAGE + row * BSTR + col) * 2,
                 Wg + (size_t)(k0 + row) * DM + n0 + col);
        }
    };

    load_stage(0, 0);
    CP_COMMIT();

    const int NIT = DM / GBK;  // 32
    for (int it = 0; it < NIT; it++) {
        const int st = it & 1;
        if (it + 1 < NIT) { load_stage(st ^ 1, (it + 1) * GBK); CP_COMMIT(); CP_WAIT1(); }
        else              { CP_WAIT0(); }
        __syncthreads();

        #pragma unroll
        for (int kk = 0; kk < 2; kk++) {
            unsigned b[4][2];
            #pragma unroll
            for (int nt2 = 0; nt2 < 2; nt2++) {
                unsigned r[4];
                ldsm4t(r, sBb + (st * B_STAGE + (kk * 16 + (lane & 15)) * BSTR
                                 + wn + nt2 * 16 + ((lane >> 4) & 1) * 8) * 2);
                b[2 * nt2][0] = r[0]; b[2 * nt2][1] = r[1];
                b[2 * nt2 + 1][0] = r[2]; b[2 * nt2 + 1][1] = r[3];
            }
            #pragma unroll
            for (int mt = 0; mt < 4; mt++) {
                unsigned a[4];
                ldsm4(a, sAb + (st * A_STAGE + (wm + mt * 16 + (lane & 15)) * ASTR
                                + kk * 16 + ((lane >> 4) & 1) * 8) * 2);
                #pragma unroll
                for (int nt = 0; nt < 4; nt++) mma16816(acc[mt][nt], a, b[nt]);
            }
        }
        __syncthreads();
    }

    const int g = lane >> 2, tg = lane & 3;
    #pragma unroll
    for (int mt = 0; mt < 4; mt++) {
        const int r = m0 + wm + mt * 16 + g;
        #pragma unroll
        for (int nt = 0; nt < 4; nt++) {
            const int col = n0 + wn + nt * 8 + 2 * tg;
            const float2 bv = *(const float2*)&bias[col];
            float v00 = (acc[mt][nt][0] + bv.x) * scale;
            float v01 = (acc[mt][nt][1] + bv.y) * scale;
            float v10 = (acc[mt][nt][2] + bv.x) * scale;
            float v11 = (acc[mt][nt][3] + bv.y) * scale;
            if (MODE == 0) {
                *(float2*)&Cf[(size_t)r * DM + col]       = make_float2(v00, v01);
                *(float2*)&Cf[(size_t)(r + 8) * DM + col] = make_float2(v10, v11);
            } else {
                const int h = col >> 6, d = col & 63;
                int bb = r >> 11, ss = r & 2047;
                *(unsigned*)&Ch[(((size_t)(bb * NH + h) * SEQ) + ss) * HD + d] = pack2(v00, v01);
                bb = (r + 8) >> 11; ss = (r + 8) & 2047;
                *(unsigned*)&Ch[(((size_t)(bb * NH + h) * SEQ) + ss) * HD + d] = pack2(v10, v11);
            }
        }
    }
}

// ---------------------------------------------------------------------------
// FlashAttention-2, fp16 mma. NOW: 256 thr (8 warps), 128 q rows per block
// (halves K/V L2 traffic vs 64-row blocks). Each warp owns 16 q rows.
// K/V double-buffered via cp.async. Q pre-scaled by 1/8. Out fp16 [B,S,DM].
// ---------------------------------------------------------------------------
#define ATS  64      // kv tile rows
#define QROWS 128    // q rows per block
#define KSTR 72
#define KV_STAGE (ATS * KSTR)   // 4608 halfs

__global__ __launch_bounds__(256) void attn_fa(
    const __half* __restrict__ Q, const __half* __restrict__ K,
    const __half* __restrict__ V, __half* __restrict__ Out)
{
    __shared__ __half sK[2 * KV_STAGE];
    __shared__ __half sV[2 * KV_STAGE];

    const int bh = blockIdx.y;
    const int q0 = blockIdx.x * QROWS;
    const int tid = threadIdx.x;
    const int warp = tid >> 5, lane = tid & 31;
    const int g = lane >> 2, tg = lane & 3;
    const size_t base = (size_t)bh * SEQ * HD;
    const unsigned sKb = smem_u32(sK), sVb = smem_u32(sV);

    // Q fragments in registers for the whole sweep: 4 k-steps x 4 regs
    unsigned qf[4][4];
    {
        const int r0 = q0 + warp * 16;
        #pragma unroll
        for (int kk = 0; kk < 4; kk++) {
            const size_t i0 = base + (size_t)(r0 + g) * HD + kk * 16 + 2 * tg;
            const size_t i1 = base + (size_t)(r0 + g + 8) * HD + kk * 16 + 2 * tg;
            qf[kk][0] = *(const unsigned*)(Q + i0);
            qf[kk][1] = *(const unsigned*)(Q + i1);
            qf[kk][2] = *(const unsigned*)(Q + i0 + 8);
            qf[kk][3] = *(const unsigned*)(Q + i1 + 8);
        }
    }

    auto load_kv = [&](int st, int kv0) {
        // per array: 64 rows x 8 chunks = 512 chunks; 256 threads -> 2 each
        #pragma unroll
        for (int c = 0; c < 2; c++) {
            int id = tid + c * 256;
            int row = id >> 3, col = (id & 7) * 8;
            size_t src = base + (size_t)(kv0 + row) * HD + col;
            unsigned off = (st * KV_STAGE + row * KSTR + col) * 2;
            cp16(sKb + off, K + src);
            cp16(sVb + off, V + src);
        }
    };

    float o[8][4];
    #pragma unroll
    for (int i = 0; i < 8; i++)
        #pragma unroll
        for (int j = 0; j < 4; j++) o[i][j] = 0.0f;
    float m0 = -1e30f, m1 = -1e30f, l0 = 0.0f, l1 = 0.0f;

    load_kv(0, 0);
    CP_COMMIT();

    const int NKV = SEQ / ATS;  // 32
    for (int it = 0; it < NKV; it++) {
        const int st = it & 1;
        if (it + 1 < NKV) { load_kv(st ^ 1, (it + 1) * ATS); CP_COMMIT(); CP_WAIT1(); }
        else              { CP_WAIT0(); }
        __syncthreads();

        // ---- S = Q @ K^T
        float s[8][4];
        #pragma unroll
        for (int i = 0; i < 8; i++)
            #pragma unroll
            for (int j = 0; j < 4; j++) s[i][j] = 0.0f;

        #pragma unroll
        for (int kk = 0; kk < 4; kk++) {
            #pragma unroll
            for (int nt2 = 0; nt2 < 4; nt2++) {
                unsigned r[4];
                ldsm4(r, sKb + (st * KV_STAGE
                                + (nt2 * 16 + ((lane >> 4) << 3) + (lane & 7)) * KSTR
                                + kk * 16 + ((lane >> 3) & 1) * 8) * 2);
                mma16816(s[2 * nt2],     qf[kk], r);
                mma16816(s[2 * nt2 + 1], qf[kk], r + 2);
            }
        }

        // ---- online softmax (rows g and g+8)
        float mx0 = -1e30f, mx1 = -1e30f;
        #pragma unroll
        for (int nt = 0; nt < 8; nt++) {
            mx0 = fmaxf(mx0, fmaxf(s[nt][0], s[nt][1]));
            mx1 = fmaxf(mx1, fmaxf(s[nt][2], s[nt][3]));
        }
        mx0 = fmaxf(mx0, __shfl_xor_sync(~0u, mx0, 1));
        mx0 = fmaxf(mx0, __shfl_xor_sync(~0u, mx0, 2));
        mx1 = fmaxf(mx1, __shfl_xor_sync(~0u, mx1, 1));
        mx1 = fmaxf(mx1, __shfl_xor_sync(~0u, mx1, 2));
        const float mn0 = fmaxf(m0, mx0), mn1 = fmaxf(m1, mx1);
        const float c0 = __expf(m0 - mn0), c1 = __expf(m1 - mn1);
        m0 = mn0; m1 = mn1;

        float ps0 = 0.f, ps1 = 0.f;
        #pragma unroll
        for (int nt = 0; nt < 8; nt++) {
            s[nt][0] = __expf(s[nt][0] - mn0);
            s[nt][1] = __expf(s[nt][1] - mn0);
            s[nt][2] = __expf(s[nt][2] - mn1);
            s[nt][3] = __expf(s[nt][3] - mn1);
            ps0 += s[nt][0] + s[nt][1];
            ps1 += s[nt][2] + s[nt][3];
        }
        ps0 += __shfl_xor_sync(~0u, ps0, 1); ps0 += __shfl_xor_sync(~0u, ps0, 2);
        ps1 += __shfl_xor_sync(~0u, ps1, 1); ps1 += __shfl_xor_sync(~0u, ps1, 2);
        l0 = l0 * c0 + ps0;
        l1 = l1 * c1 + ps1;

        #pragma unroll
        for (int nt = 0; nt < 8; nt++) {
            o[nt][0] *= c0; o[nt][1] *= c0; o[nt][2] *= c1; o[nt][3] *= c1;
        }

        // ---- P fragments
        unsigned pa[4][4];
        #pragma unroll
        for (int kk = 0; kk < 4; kk++) {
            pa[kk][0] = pack2(s[2 * kk][0],     s[2 * kk][1]);
            pa[kk][1] = pack2(s[2 * kk][2],     s[2 * kk][3]);
            pa[kk][2] = pack2(s[2 * kk + 1][0], s[2 * kk + 1][1]);
            pa[kk][3] = pack2(s[2 * kk + 1][2], s[2 * kk + 1][3]);
        }

        // ---- O += P @ V
        #pragma unroll
        for (int kk = 0; kk < 4; kk++) {
            #pragma unroll
            for (int nt2 = 0; nt2 < 4; nt2++) {
                unsigned r[4];
                ldsm4t(r, sVb + (st * KV_STAGE + (kk * 16 + (lane & 15)) * KSTR
                                 + nt2 * 16 + ((lane >> 4) & 1) * 8) * 2);
                mma16816(o[2 * nt2],     pa[kk], r);
                mma16816(o[2 * nt2 + 1], pa[kk], r + 2);
            }
        }
        __syncthreads();
    }

    // ---- write out [B,S,DM] fp16
    const float i0 = 1.0f / l0, i1 = 1.0f / l1;
    const int b = bh / NH, h = bh % NH;
    const size_t tok = (size_t)b * SEQ + q0 + warp * 16 + g;
    #pragma unroll
    for (int nt = 0; nt < 8; nt++) {
        const int col = h * HD + nt * 8 + 2 * tg;
        *(unsigned*)&Out[tok * DM + col]       = pack2(o[nt][0] * i0, o[nt][1] * i0);
        *(unsigned*)&Out[(tok + 8) * DM + col] = pack2(o[nt][2] * i1, o[nt][3] * i1);
    }
}

// ---------------------------------------------------------------------------
// Residual + LayerNorm (one 256-thr block per token row)
// ---------------------------------------------------------------------------
__global__ __launch_bounds__(256) void ln_kernel(
    const float* __restrict__ X, const float* __restrict__ P,
    const float* __restrict__ gamma, const float* __restrict__ beta,
    float* __restrict__ out)
{
    const int r = blockIdx.x, t = threadIdx.x;
    const float4 x4 = ((const float4*)(X + (size_t)r * DM))[t];
    const float4 p4 = ((const float4*)(P + (size_t)r * DM))[t];
    float v0 = x4.x + p4.x, v1 = x4.y + p4.y, v2 = x4.z + p4.z, v3 = x4.w + p4.w;

    __shared__ float red[8];
    __shared__ float s_mu, s_rstd;

    float s = v0 + v1 + v2 + v3;
    #pragma unroll
    for (int off = 16; off > 0; off >>= 1) s += __shfl_xor_sync(~0u, s, off);
    if ((t & 31) == 0) red[t >> 5] = s;
    __syncthreads();
    if (t == 0) {
        float tot = 0.f;
        #pragma unroll
        for (int i = 0; i < 8; i++) tot += red[i];
        s_mu = tot * (1.0f / DM);
    }
    __syncthreads();
    const float mu = s_mu;
    float d0 = v0 - mu, d1 = v1 - mu, d2 = v2 - mu, d3 = v3 - mu;
    float sq = d0 * d0 + d1 * d1 + d2 * d2 + d3 * d3;
    #pragma unroll
    for (int off = 16; off > 0; off >>= 1) sq += __shfl_xor_sync(~0u, sq, off);
    if ((t & 31) == 0) red[t >> 5] = sq;
    __syncthreads();
    if (t == 0) {
        float tot = 0.f;
        #pragma unroll
        for (int i = 0; i < 8; i++) tot += red[i];
        s_rstd = rsqrtf(tot * (1.0f / DM) + LN_EPS);
    }
    __syncthreads();
    const float rstd = s_rstd;

    const float4 g4 = ((const float4*)gamma)[t];
    const float4 b4 = ((const float4*)beta)[t];
    float4 o4;
    o4.x = d0 * rstd * g4.x + b4.x;
    o4.y = d1 * rstd * g4.y + b4.y;
    o4.z = d2 * rstd * g4.z + b4.z;
    o4.w = d3 * rstd * g4.w + b4.w;
    ((float4*)(out + (size_t)r * DM))[t] = o4;
}

// ---------------------------------------------------------------------------
// Launch (ordering puts attn_fa at launch #6 for the ncu -s 5 -c 1 window)
// ---------------------------------------------------------------------------
extern "C" void kernel_launch(void* const* d_in, const int* in_sizes, int n_in,
                              void* d_out, int out_size)
{
    const float* x     = (const float*)d_in[0];
    const float* Wq    = (const float*)d_in[1];
    const float* bq    = (const float*)d_in[2];
    const float* Wk    = (const float*)d_in[3];
    const float* bk    = (const float*)d_in[4];
    const float* Wv    = (const float*)d_in[5];
    const float* bv    = (const float*)d_in[6];
    const float* Wo    = (const float*)d_in[7];
    const float* bo    = (const float*)d_in[8];
    const float* gamma = (const float*)d_in[9];
    const float* beta  = (const float*)d_in[10];
    float* out = (float*)d_out;

    __half *hx, *hwq, *hwk, *hwv, *hwo, *q, *k, *v, *ah;
    float *proj;
    cudaGetSymbolAddress((void**)&hx,  g_hx);
    cudaGetSymbolAddress((void**)&hwq, g_hwq);
    cudaGetSymbolAddress((void**)&hwk, g_hwk);
    cudaGetSymbolAddress((void**)&hwv, g_hwv);
    cudaGetSymbolAddress((void**)&hwo, g_hwo);
    cudaGetSymbolAddress((void**)&q,   g_q);
    cudaGetSymbolAddress((void**)&k,   g_k);
    cudaGetSymbolAddress((void**)&v,   g_v);
    cudaGetSymbolAddress((void**)&ah,  g_ah);
    cudaGetSymbolAddress((void**)&proj, g_proj);

    cvt_kernel<<<NTOK * DM / 1024, 256>>>(x, hx, NTOK * DM);                    // #1
    cvt_w_kernel<<<dim3(DM * DM / 1024, 4), 256>>>(Wq, Wk, Wv, Wo,
                                                   hwq, hwk, hwv, hwo);         // #2

    dim3 ggrid(DM / GBN, NTOK / GBM);   // (8, 64)
    gemm_h<1><<<ggrid, 256>>>(hx, hwq, bq, 0.125f, nullptr, q);                 // #3
    gemm_h<1><<<ggrid, 256>>>(hx, hwk, bk, 1.0f,   nullptr, k);                 // #4
    gemm_h<1><<<ggrid, 256>>>(hx, hwv, bv, 1.0f,   nullptr, v);                 // #5

    attn_fa<<<dim3(SEQ / QROWS, BATCH * NH), 256>>>(q, k, v, ah);               // #6

    gemm_h<0><<<ggrid, 256>>>(ah, hwo, bo, 1.0f, proj, nullptr);                // #7

    ln_kernel<<<NTOK, 256>>>(x, proj, gamma, beta, out);                        // #8
}

// round 9
// speedup vs baseline: 1.0649x; 1.0649x over previous
#include <cuda_runtime.h>
#include <cuda_fp16.h>
#include <math.h>

#define BATCH 4
#define SEQ   2048
#define DM    1024
#define NH    16
#define HD    64
#define NTOK  (BATCH * SEQ)   // 8192
#define LN_EPS 1e-6f

// ---------------------------------------------------------------------------
// Device-global scratch
// ---------------------------------------------------------------------------
__device__ __half g_hx[NTOK * DM];
__device__ __half g_hwq[DM * DM], g_hwk[DM * DM], g_hwv[DM * DM], g_hwo[DM * DM];
__device__ __half g_q[NTOK * DM];             // [B,H,S,HD] (pre-scaled 1/8)
__device__ __half g_k[NTOK * DM];
__device__ __half g_v[NTOK * DM];
__device__ __half g_ah[NTOK * DM];            // attn out [B,S,DM]
__device__ float  g_proj[NTOK * DM];

// ---------------------------------------------------------------------------
// PTX helpers
// ---------------------------------------------------------------------------
__device__ __forceinline__ unsigned smem_u32(const void* p) {
    return (unsigned)__cvta_generic_to_shared(p);
}
__device__ __forceinline__ void ldsm4(unsigned* r, unsigned a) {
    asm volatile("ldmatrix.sync.aligned.m8n8.x4.shared.b16 {%0,%1,%2,%3},[%4];"
                 : "=r"(r[0]), "=r"(r[1]), "=r"(r[2]), "=r"(r[3]) : "r"(a));
}
__device__ __forceinline__ void ldsm4t(unsigned* r, unsigned a) {
    asm volatile("ldmatrix.sync.aligned.m8n8.x4.trans.shared.b16 {%0,%1,%2,%3},[%4];"
                 : "=r"(r[0]), "=r"(r[1]), "=r"(r[2]), "=r"(r[3]) : "r"(a));
}
__device__ __forceinline__ void mma16816(float* c, const unsigned* a, const unsigned* b) {
    asm volatile(
        "mma.sync.aligned.m16n8k16.row.col.f32.f16.f16.f32 "
        "{%0,%1,%2,%3},{%4,%5,%6,%7},{%8,%9},{%0,%1,%2,%3};"
        : "+f"(c[0]), "+f"(c[1]), "+f"(c[2]), "+f"(c[3])
        : "r"(a[0]), "r"(a[1]), "r"(a[2]), "r"(a[3]), "r"(b[0]), "r"(b[1]));
}
__device__ __forceinline__ void cp16(unsigned dst, const void* src) {
    asm volatile("cp.async.cg.shared.global [%0],[%1],16;" :: "r"(dst), "l"(src));
}
#define CP_COMMIT() asm volatile("cp.async.commit_group;")
#define CP_WAIT1()  asm volatile("cp.async.wait_group 1;")
#define CP_WAIT0()  asm volatile("cp.async.wait_group 0;")

__device__ __forceinline__ unsigned pack2(float x, float y) {
    __half2 h = __floats2half2_rn(x, y);
    return *reinterpret_cast<unsigned*>(&h);
}

// ---------------------------------------------------------------------------
// fp32 -> fp16 converts
// ---------------------------------------------------------------------------
__global__ __launch_bounds__(256) void cvt_kernel(
    const float* __restrict__ in, __half* __restrict__ out, int n)
{
    int i = (blockIdx.x * 256 + threadIdx.x) * 4;
    if (i >= n) return;
    float4 v = *(const float4*)(in + i);
    *(unsigned*)(out + i)     = pack2(v.x, v.y);
    *(unsigned*)(out + i + 2) = pack2(v.z, v.w);
}

__global__ __launch_bounds__(256) void cvt_w_kernel(
    const float* __restrict__ W0, const float* __restrict__ W1,
    const float* __restrict__ W2, const float* __restrict__ W3,
    __half* __restrict__ O0, __half* __restrict__ O1,
    __half* __restrict__ O2, __half* __restrict__ O3)
{
    const float* W; __half* O;
    switch (blockIdx.y) {
        case 0: W = W0; O = O0; break;
        case 1: W = W1; O = O1; break;
        case 2: W = W2; O = O2; break;
        default: W = W3; O = O3; break;
    }
    int i = (blockIdx.x * 256 + threadIdx.x) * 4;
    float4 v = *(const float4*)(W + i);
    *(unsigned*)(O + i)     = pack2(v.x, v.y);
    *(unsigned*)(O + i + 2) = pack2(v.z, v.w);
}

// ---------------------------------------------------------------------------
// fp16 mma GEMM: C = A @ W + bias.  BM=BN=128, BK=64 (barriers halved vs R6),
// 256 thr (8 warps 2x4), warp tile 64x32, double-buffered cp.async, dyn smem.
// MODE 1: fp16 head-split out, scaled. MODE 0: fp32 row-major.
// ---------------------------------------------------------------------------
#define GBM 128
#define GBN 128
#define GBK 64
#define ASTR 72                 // 64 + 8 pad (halfs)
#define BSTR 136                // 128 + 8 pad
#define A_STAGE (GBM * ASTR)    // 9216 halfs
#define B_STAGE (GBK * BSTR)    // 8704 halfs
#define GEMM_SMEM ((2 * A_STAGE + 2 * B_STAGE) * 2)  // 71680 B

template <int MODE>
__global__ __launch_bounds__(256) void gemm_h(
    const __half* __restrict__ Ag, const __half* __restrict__ Wg,
    const float* __restrict__ bias, float scale,
    float* __restrict__ Cf, __half* __restrict__ Ch)
{
    extern __shared__ __half smem[];
    __half* sA = smem;                    // 2 stages
    __half* sB = smem + 2 * A_STAGE;

    const int tid = threadIdx.x;
    const int lane = tid & 31, warp = tid >> 5;
    const int wm = (warp >> 2) * 64;
    const int wn = (warp & 3) * 32;
    const int m0 = blockIdx.y * GBM;
    const int n0 = blockIdx.x * GBN;
    const unsigned sAb = smem_u32(sA), sBb = smem_u32(sB);

    float acc[4][4][4];
    #pragma unroll
    for (int i = 0; i < 4; i++)
        #pragma unroll
        for (int j = 0; j < 4; j++)
            #pragma unroll
            for (int r = 0; r < 4; r++) acc[i][j][r] = 0.0f;

    auto load_stage = [&](int st, int k0) {
        // A: 128 rows x 64 halfs = 1024 16B chunks; 4 per thread
        #pragma unroll
        for (int c = 0; c < 4; c++) {
            int id = tid + c * 256;
            int row = id >> 3, col = (id & 7) * 8;
            cp16(sAb + (st * A_STAGE + row * ASTR + col) * 2,
                 Ag + (size_t)(m0 + row) * DM + k0 + col);
        }
        // B: 64 rows x 128 halfs = 1024 chunks; 4 per thread
        #pragma unroll
        for (int c = 0; c < 4; c++) {
            int id = tid + c * 256;
            int row = id >> 4, col = (id & 15) * 8;
            cp16(sBb + (st * B_STAGE + row * BSTR + col) * 2,
                 Wg + (size_t)(k0 + row) * DM + n0 + col);
        }
    };

    load_stage(0, 0);
    CP_COMMIT();

    const int NIT = DM / GBK;  // 16
    for (int it = 0; it < NIT; it++) {
        const int st = it & 1;
        if (it + 1 < NIT) { load_stage(st ^ 1, (it + 1) * GBK); CP_COMMIT(); CP_WAIT1(); }
        else              { CP_WAIT0(); }
        __syncthreads();

        #pragma unroll
        for (int kk = 0; kk < 4; kk++) {   // 4 x K16 per BK=64
            unsigned b[4][2];
            #pragma unroll
            for (int nt2 = 0; nt2 < 2; nt2++) {
                unsigned r[4];
                ldsm4t(r, sBb + (st * B_STAGE + (kk * 16 + (lane & 15)) * BSTR
                                 + wn + nt2 * 16 + ((lane >> 4) & 1) * 8) * 2);
                b[2 * nt2][0] = r[0]; b[2 * nt2][1] = r[1];
                b[2 * nt2 + 1][0] = r[2]; b[2 * nt2 + 1][1] = r[3];
            }
            #pragma unroll
            for (int mt = 0; mt < 4; mt++) {
                unsigned a[4];
                ldsm4(a, sAb + (st * A_STAGE + (wm + mt * 16 + (lane & 15)) * ASTR
                                + kk * 16 + ((lane >> 4) & 1) * 8) * 2);
                #pragma unroll
                for (int nt = 0; nt < 4; nt++) mma16816(acc[mt][nt], a, b[nt]);
            }
        }
        __syncthreads();
    }

    const int g = lane >> 2, tg = lane & 3;
    #pragma unroll
    for (int mt = 0; mt < 4; mt++) {
        const int r = m0 + wm + mt * 16 + g;
        #pragma unroll
        for (int nt = 0; nt < 4; nt++) {
            const int col = n0 + wn + nt * 8 + 2 * tg;
            const float2 bv = *(const float2*)&bias[col];
            float v00 = (acc[mt][nt][0] + bv.x) * scale;
            float v01 = (acc[mt][nt][1] + bv.y) * scale;
            float v10 = (acc[mt][nt][2] + bv.x) * scale;
            float v11 = (acc[mt][nt][3] + bv.y) * scale;
            if (MODE == 0) {
                *(float2*)&Cf[(size_t)r * DM + col]       = make_float2(v00, v01);
                *(float2*)&Cf[(size_t)(r + 8) * DM + col] = make_float2(v10, v11);
            } else {
                const int h = col >> 6, d = col & 63;
                int bb = r >> 11, ss = r & 2047;
                *(unsigned*)&Ch[(((size_t)(bb * NH + h) * SEQ) + ss) * HD + d] = pack2(v00, v01);
                bb = (r + 8) >> 11; ss = (r + 8) & 2047;
                *(unsigned*)&Ch[(((size_t)(bb * NH + h) * SEQ) + ss) * HD + d] = pack2(v10, v11);
            }
        }
    }
}

// ---------------------------------------------------------------------------
// FlashAttention-2, fp16 mma (R6-proven config: 128 thr, 64 q rows/block)
// ---------------------------------------------------------------------------
#define ATS 64
#define KSTR 72
#define KV_STAGE (ATS * KSTR)

__global__ __launch_bounds__(128) void attn_fa(
    const __half* __restrict__ Q, const __half* __restrict__ K,
    const __half* __restrict__ V, __half* __restrict__ Out)
{
    __shared__ __half sK[2 * KV_STAGE];
    __shared__ __half sV[2 * KV_STAGE];

    const int bh = blockIdx.y;
    const int q0 = blockIdx.x * ATS;
    const int tid = threadIdx.x;
    const int warp = tid >> 5, lane = tid & 31;
    const int g = lane >> 2, tg = lane & 3;
    const size_t base = (size_t)bh * SEQ * HD;
    const unsigned sKb = smem_u32(sK), sVb = smem_u32(sV);

    unsigned qf[4][4];
    {
        const int r0 = q0 + warp * 16;
        #pragma unroll
        for (int kk = 0; kk < 4; kk++) {
            const size_t i0 = base + (size_t)(r0 + g) * HD + kk * 16 + 2 * tg;
            const size_t i1 = base + (size_t)(r0 + g + 8) * HD + kk * 16 + 2 * tg;
            qf[kk][0] = *(const unsigned*)(Q + i0);
            qf[kk][1] = *(const unsigned*)(Q + i1);
            qf[kk][2] = *(const unsigned*)(Q + i0 + 8);
            qf[kk][3] = *(const unsigned*)(Q + i1 + 8);
        }
    }

    auto load_kv = [&](int st, int kv0) {
        #pragma unroll
        for (int c = 0; c < 4; c++) {
            int id = tid + c * 128;
            int row = id >> 3, col = (id & 7) * 8;
            size_t src = base + (size_t)(kv0 + row) * HD + col;
            unsigned off = (st * KV_STAGE + row * KSTR + col) * 2;
            cp16(sKb + off, K + src);
            cp16(sVb + off, V + src);
        }
    };

    float o[8][4];
    #pragma unroll
    for (int i = 0; i < 8; i++)
        #pragma unroll
        for (int j = 0; j < 4; j++) o[i][j] = 0.0f;
    float m0 = -1e30f, m1 = -1e30f, l0 = 0.0f, l1 = 0.0f;

    load_kv(0, 0);
    CP_COMMIT();

    const int NKV = SEQ / ATS;
    for (int it = 0; it < NKV; it++) {
        const int st = it & 1;
        if (it + 1 < NKV) { load_kv(st ^ 1, (it + 1) * ATS); CP_COMMIT(); CP_WAIT1(); }
        else              { CP_WAIT0(); }
        __syncthreads();

        float s[8][4];
        #pragma unroll
        for (int i = 0; i < 8; i++)
            #pragma unroll
            for (int j = 0; j < 4; j++) s[i][j] = 0.0f;

        #pragma unroll
        for (int kk = 0; kk < 4; kk++) {
            #pragma unroll
            for (int nt2 = 0; nt2 < 4; nt2++) {
                unsigned r[4];
                ldsm4(r, sKb + (st * KV_STAGE
                                + (nt2 * 16 + ((lane >> 4) << 3) + (lane & 7)) * KSTR
                                + kk * 16 + ((lane >> 3) & 1) * 8) * 2);
                mma16816(s[2 * nt2],     qf[kk], r);
                mma16816(s[2 * nt2 + 1], qf[kk], r + 2);
            }
        }

        float mx0 = -1e30f, mx1 = -1e30f;
        #pragma unroll
        for (int nt = 0; nt < 8; nt++) {
            mx0 = fmaxf(mx0, fmaxf(s[nt][0], s[nt][1]));
            mx1 = fmaxf(mx1, fmaxf(s[nt][2], s[nt][3]));
        }
        mx0 = fmaxf(mx0, __shfl_xor_sync(~0u, mx0, 1));
        mx0 = fmaxf(mx0, __shfl_xor_sync(~0u, mx0, 2));
        mx1 = fmaxf(mx1, __shfl_xor_sync(~0u, mx1, 1));
        mx1 = fmaxf(mx1, __shfl_xor_sync(~0u, mx1, 2));
        const float mn0 = fmaxf(m0, mx0), mn1 = fmaxf(m1, mx1);
        const float c0 = __expf(m0 - mn0), c1 = __expf(m1 - mn1);
        m0 = mn0; m1 = mn1;

        float ps0 = 0.f, ps1 = 0.f;
        #pragma unroll
        for (int nt = 0; nt < 8; nt++) {
            s[nt][0] = __expf(s[nt][0] - mn0);
            s[nt][1] = __expf(s[nt][1] - mn0);
            s[nt][2] = __expf(s[nt][2] - mn1);
            s[nt][3] = __expf(s[nt][3] - mn1);
            ps0 += s[nt][0] + s[nt][1];
            ps1 += s[nt][2] + s[nt][3];
        }
        ps0 += __shfl_xor_sync(~0u, ps0, 1); ps0 += __shfl_xor_sync(~0u, ps0, 2);
        ps1 += __shfl_xor_sync(~0u, ps1, 1); ps1 += __shfl_xor_sync(~0u, ps1, 2);
        l0 = l0 * c0 + ps0;
        l1 = l1 * c1 + ps1;

        #pragma unroll
        for (int nt = 0; nt < 8; nt++) {
            o[nt][0] *= c0; o[nt][1] *= c0; o[nt][2] *= c1; o[nt][3] *= c1;
        }

        unsigned pa[4][4];
        #pragma unroll
        for (int kk = 0; kk < 4; kk++) {
            pa[kk][0] = pack2(s[2 * kk][0],     s[2 * kk][1]);
            pa[kk][1] = pack2(s[2 * kk][2],     s[2 * kk][3]);
            pa[kk][2] = pack2(s[2 * kk + 1][0], s[2 * kk + 1][1]);
            pa[kk][3] = pack2(s[2 * kk + 1][2], s[2 * kk + 1][3]);
        }

        #pragma unroll
        for (int kk = 0; kk < 4; kk++) {
            #pragma unroll
            for (int nt2 = 0; nt2 < 4; nt2++) {
                unsigned r[4];
                ldsm4t(r, sVb + (st * KV_STAGE + (kk * 16 + (lane & 15)) * KSTR
                                 + nt2 * 16 + ((lane >> 4) & 1) * 8) * 2);
                mma16816(o[2 * nt2],     pa[kk], r);
                mma16816(o[2 * nt2 + 1], pa[kk], r + 2);
            }
        }
        __syncthreads();
    }

    const float i0 = 1.0f / l0, i1 = 1.0f / l1;
    const int b = bh / NH, h = bh % NH;
    const size_t tok = (size_t)b * SEQ + q0 + warp * 16 + g;
    #pragma unroll
    for (int nt = 0; nt < 8; nt++) {
        const int col = h * HD + nt * 8 + 2 * tg;
        *(unsigned*)&Out[tok * DM + col]       = pack2(o[nt][0] * i0, o[nt][1] * i0);
        *(unsigned*)&Out[(tok + 8) * DM + col] = pack2(o[nt][2] * i1, o[nt][3] * i1);
    }
}

// ---------------------------------------------------------------------------
// Residual + LayerNorm
// ---------------------------------------------------------------------------
__global__ __launch_bounds__(256) void ln_kernel(
    const float* __restrict__ X, const float* __restrict__ P,
    const float* __restrict__ gamma, const float* __restrict__ beta,
    float* __restrict__ out)
{
    const int r = blockIdx.x, t = threadIdx.x;
    const float4 x4 = ((const float4*)(X + (size_t)r * DM))[t];
    const float4 p4 = ((const float4*)(P + (size_t)r * DM))[t];
    float v0 = x4.x + p4.x, v1 = x4.y + p4.y, v2 = x4.z + p4.z, v3 = x4.w + p4.w;

    __shared__ float red[8];
    __shared__ float s_mu, s_rstd;

    float s = v0 + v1 + v2 + v3;
    #pragma unroll
    for (int off = 16; off > 0; off >>= 1) s += __shfl_xor_sync(~0u, s, off);
    if ((t & 31) == 0) red[t >> 5] = s;
    __syncthreads();
    if (t == 0) {
        float tot = 0.f;
        #pragma unroll
        for (int i = 0; i < 8; i++) tot += red[i];
        s_mu = tot * (1.0f / DM);
    }
    __syncthreads();
    const float mu = s_mu;
    float d0 = v0 - mu, d1 = v1 - mu, d2 = v2 - mu, d3 = v3 - mu;
    float sq = d0 * d0 + d1 * d1 + d2 * d2 + d3 * d3;
    #pragma unroll
    for (int off = 16; off > 0; off >>= 1) sq += __shfl_xor_sync(~0u, sq, off);
    if ((t & 31) == 0) red[t >> 5] = sq;
    __syncthreads();
    if (t == 0) {
        float tot = 0.f;
        #pragma unroll
        for (int i = 0; i < 8; i++) tot += red[i];
        s_rstd = rsqrtf(tot * (1.0f / DM) + LN_EPS);
    }
    __syncthreads();
    const float rstd = s_rstd;

    const float4 g4 = ((const float4*)gamma)[t];
    const float4 b4 = ((const float4*)beta)[t];
    float4 o4;
    o4.x = d0 * rstd * g4.x + b4.x;
    o4.y = d1 * rstd * g4.y + b4.y;
    o4.z = d2 * rstd * g4.z + b4.z;
    o4.w = d3 * rstd * g4.w + b4.w;
    ((float4*)(out + (size_t)r * DM))[t] = o4;
}

// ---------------------------------------------------------------------------
// Launch
// ---------------------------------------------------------------------------
extern "C" void kernel_launch(void* const* d_in, const int* in_sizes, int n_in,
                              void* d_out, int out_size)
{
    const float* x     = (const float*)d_in[0];
    const float* Wq    = (const float*)d_in[1];
    const float* bq    = (const float*)d_in[2];
    const float* Wk    = (const float*)d_in[3];
    const float* bk    = (const float*)d_in[4];
    const float* Wv    = (const float*)d_in[5];
    const float* bv    = (const float*)d_in[6];
    const float* Wo    = (const float*)d_in[7];
    const float* bo    = (const float*)d_in[8];
    const float* gamma = (const float*)d_in[9];
    const float* beta  = (const float*)d_in[10];
    float* out = (float*)d_out;

    __half *hx, *hwq, *hwk, *hwv, *hwo, *q, *k, *v, *ah;
    float *proj;
    cudaGetSymbolAddress((void**)&hx,  g_hx);
    cudaGetSymbolAddress((void**)&hwq, g_hwq);
    cudaGetSymbolAddress((void**)&hwk, g_hwk);
    cudaGetSymbolAddress((void**)&hwv, g_hwv);
    cudaGetSymbolAddress((void**)&hwo, g_hwo);
    cudaGetSymbolAddress((void**)&q,   g_q);
    cudaGetSymbolAddress((void**)&k,   g_k);
    cudaGetSymbolAddress((void**)&v,   g_v);
    cudaGetSymbolAddress((void**)&ah,  g_ah);
    cudaGetSymbolAddress((void**)&proj, g_proj);

    cudaFuncSetAttribute(gemm_h<0>, cudaFuncAttributeMaxDynamicSharedMemorySize, GEMM_SMEM);
    cudaFuncSetAttribute(gemm_h<1>, cudaFuncAttributeMaxDynamicSharedMemorySize, GEMM_SMEM);

    cvt_kernel<<<NTOK * DM / 1024, 256>>>(x, hx, NTOK * DM);
    cvt_w_kernel<<<dim3(DM * DM / 1024, 4), 256>>>(Wq, Wk, Wv, Wo,
                                                   hwq, hwk, hwv, hwo);

    dim3 ggrid(DM / GBN, NTOK / GBM);   // (8, 64)
    gemm_h<1><<<ggrid, 256, GEMM_SMEM>>>(hx, hwq, bq, 0.125f, nullptr, q);
    gemm_h<1><<<ggrid, 256, GEMM_SMEM>>>(hx, hwk, bk, 1.0f,   nullptr, k);
    gemm_h<1><<<ggrid, 256, GEMM_SMEM>>>(hx, hwv, bv, 1.0f,   nullptr, v);

    attn_fa<<<dim3(SEQ / ATS, BATCH * NH), 128>>>(q, k, v, ah);

    gemm_h<0><<<ggrid, 256, GEMM_SMEM>>>(ah, hwo, bo, 1.0f, proj, nullptr);

    ln_kernel<<<NTOK, 256>>>(x, proj, gamma, beta, out);
}

// round 11
// speedup vs baseline: 1.1475x; 1.0776x over previous
#include <cuda_runtime.h>
#include <cuda_fp16.h>
#include <math.h>

#define BATCH 4
#define SEQ   2048
#define DM    1024
#define NH    16
#define HD    64
#define NTOK  (BATCH * SEQ)   // 8192
#define LN_EPS 1e-6f
// 1/sqrt(64) * log2(e) folded into Q projection so softmax can use raw exp2
#define QSCALE 0.18033688011112042f

// ---------------------------------------------------------------------------
// Device-global scratch
// ---------------------------------------------------------------------------
__device__ __half g_hx[NTOK * DM];
__device__ __half g_hwq[DM * DM], g_hwk[DM * DM], g_hwv[DM * DM], g_hwo[DM * DM];
__device__ __half g_q[NTOK * DM];             // [B,H,S,HD] (pre-scaled by QSCALE)
__device__ __half g_k[NTOK * DM];
__device__ __half g_v[NTOK * DM];
__device__ __half g_ah[NTOK * DM];            // attn out [B,S,DM]
__device__ float  g_proj[NTOK * DM];

// ---------------------------------------------------------------------------
// PTX helpers
// ---------------------------------------------------------------------------
__device__ __forceinline__ unsigned smem_u32(const void* p) {
    return (unsigned)__cvta_generic_to_shared(p);
}
__device__ __forceinline__ void ldsm4(unsigned* r, unsigned a) {
    asm volatile("ldmatrix.sync.aligned.m8n8.x4.shared.b16 {%0,%1,%2,%3},[%4];"
                 : "=r"(r[0]), "=r"(r[1]), "=r"(r[2]), "=r"(r[3]) : "r"(a));
}
__device__ __forceinline__ void ldsm4t(unsigned* r, unsigned a) {
    asm volatile("ldmatrix.sync.aligned.m8n8.x4.trans.shared.b16 {%0,%1,%2,%3},[%4];"
                 : "=r"(r[0]), "=r"(r[1]), "=r"(r[2]), "=r"(r[3]) : "r"(a));
}
__device__ __forceinline__ void mma16816(float* c, const unsigned* a, const unsigned* b) {
    asm volatile(
        "mma.sync.aligned.m16n8k16.row.col.f32.f16.f16.f32 "
        "{%0,%1,%2,%3},{%4,%5,%6,%7},{%8,%9},{%0,%1,%2,%3};"
        : "+f"(c[0]), "+f"(c[1]), "+f"(c[2]), "+f"(c[3])
        : "r"(a[0]), "r"(a[1]), "r"(a[2]), "r"(a[3]), "r"(b[0]), "r"(b[1]));
}
__device__ __forceinline__ void cp16(unsigned dst, const void* src) {
    asm volatile("cp.async.cg.shared.global [%0],[%1],16;" :: "r"(dst), "l"(src));
}
#define CP_COMMIT() asm volatile("cp.async.commit_group;")
#define CP_WAIT2()  asm volatile("cp.async.wait_group 2;")
#define CP_WAIT1()  asm volatile("cp.async.wait_group 1;")
#define CP_WAIT0()  asm volatile("cp.async.wait_group 0;")

__device__ __forceinline__ unsigned pack2(float x, float y) {
    __half2 h = __floats2half2_rn(x, y);
    return *reinterpret_cast<unsigned*>(&h);
}
__device__ __forceinline__ float ex2f(float x) {
    float r;
    asm("ex2.approx.ftz.f32 %0, %1;" : "=f"(r) : "f"(x));
    return r;
}

// ---------------------------------------------------------------------------
// fp32 -> fp16 converts
// ---------------------------------------------------------------------------
__global__ __launch_bounds__(256) void cvt_kernel(
    const float* __restrict__ in, __half* __restrict__ out, int n)
{
    int i = (blockIdx.x * 256 + threadIdx.x) * 4;
    if (i >= n) return;
    float4 v = *(const float4*)(in + i);
    *(unsigned*)(out + i)     = pack2(v.x, v.y);
    *(unsigned*)(out + i + 2) = pack2(v.z, v.w);
}

__global__ __launch_bounds__(256) void cvt_w_kernel(
    const float* __restrict__ W0, const float* __restrict__ W1,
    const float* __restrict__ W2, const float* __restrict__ W3,
    __half* __restrict__ O0, __half* __restrict__ O1,
    __half* __restrict__ O2, __half* __restrict__ O3)
{
    const float* W; __half* O;
    switch (blockIdx.y) {
        case 0: W = W0; O = O0; break;
        case 1: W = W1; O = O1; break;
        case 2: W = W2; O = O2; break;
        default: W = W3; O = O3; break;
    }
    int i = (blockIdx.x * 256 + threadIdx.x) * 4;
    float4 v = *(const float4*)(W + i);
    *(unsigned*)(O + i)     = pack2(v.x, v.y);
    *(unsigned*)(O + i + 2) = pack2(v.z, v.w);
}

// ---------------------------------------------------------------------------
// fp16 mma GEMM. BM=BN=128, BK=64, 3-stage cp.async pipeline, 256 thr
// (8 warps 2x4), warp tile 64x32, dynamic smem 107.5KB (2 CTAs/SM).
// MODE 1: fused QKV — blockIdx.z selects weights/bias/output; fp16
//         head-split out, z==0 scaled by QSCALE. MODE 0: single GEMM,
//         fp32 row-major out (O projection).
// ---------------------------------------------------------------------------
#define GBM 128
#define GBN 128
#define GBK 64
#define ASTR 72                 // 64 + 8 pad (halfs)
#define BSTR 136                // 128 + 8 pad
#define A_STAGE (GBM * ASTR)    // 9216 halfs
#define B_STAGE (GBK * BSTR)    // 8704 halfs
#define NSTAGE 3
#define GEMM_SMEM (NSTAGE * (A_STAGE + B_STAGE) * 2)  // 107520 B

template <int MODE>
__global__ __launch_bounds__(256) void gemm_h(
    const __half* __restrict__ Ag,
    const __half* __restrict__ W0g, const __half* __restrict__ W1g,
    const __half* __restrict__ W2g,
    const float* __restrict__ b0, const float* __restrict__ b1,
    const float* __restrict__ b2,
    float* __restrict__ Cf,
    __half* __restrict__ C0, __half* __restrict__ C1, __half* __restrict__ C2)
{
    extern __shared__ __half smem[];
    __half* sA = smem;                        // NSTAGE stages
    __half* sB = smem + NSTAGE * A_STAGE;

    const __half* Wg; const float* bias; __half* Ch; float scale;
    if (MODE == 1) {
        switch (blockIdx.z) {
            case 0:  Wg = W0g; bias = b0; Ch = C0; scale = QSCALE; break;
            case 1:  Wg = W1g; bias = b1; Ch = C1; scale = 1.0f;   break;
            default: Wg = W2g; bias = b2; Ch = C2; scale = 1.0f;   break;
        }
    } else {
        Wg = W0g; bias = b0; Ch = nullptr; scale = 1.0f;
    }

    const int tid = threadIdx.x;
    const int lane = tid & 31, warp = tid >> 5;
    const int wm = (warp >> 2) * 64;
    const int wn = (warp & 3) * 32;
    const int m0 = blockIdx.y * GBM;
    const int n0 = blockIdx.x * GBN;
    const unsigned sAb = smem_u32(sA), sBb = smem_u32(sB);

    float acc[4][4][4];
    #pragma unroll
    for (int i = 0; i < 4; i++)
        #pragma unroll
        for (int j = 0; j < 4; j++)
            #pragma unroll
            for (int r = 0; r < 4; r++) acc[i][j][r] = 0.0f;

    auto load_stage = [&](int st, int k0) {
        #pragma unroll
        for (int c = 0; c < 4; c++) {
            int id = tid + c * 256;
            int row = id >> 3, col = (id & 7) * 8;
            cp16(sAb + (st * A_STAGE + row * ASTR + col) * 2,
                 Ag + (size_t)(m0 + row) * DM + k0 + col);
        }
        #pragma unroll
        for (int c = 0; c < 4; c++) {
            int id = tid + c * 256;
            int row = id >> 4, col = (id & 15) * 8;
            cp16(sBb + (st * B_STAGE + row * BSTR + col) * 2,
                 Wg + (size_t)(k0 + row) * DM + n0 + col);
        }
    };

    load_stage(0, 0);       CP_COMMIT();
    load_stage(1, GBK);     CP_COMMIT();

    const int NIT = DM / GBK;  // 16
    int cur = 0;
    for (int it = 0; it < NIT; it++) {
        if (it + 2 < NIT) {
            int nst = cur + 2; if (nst >= NSTAGE) nst -= NSTAGE;
            load_stage(nst, (it + 2) * GBK);
            CP_COMMIT();
            CP_WAIT2();
        } else if (it + 1 < NIT) { CP_WAIT1(); }
        else                     { CP_WAIT0(); }
        __syncthreads();

        #pragma unroll
        for (int kk = 0; kk < 4; kk++) {   // 4 x K16 per BK=64
            unsigned b[4][2];
            #pragma unroll
            for (int nt2 = 0; nt2 < 2; nt2++) {
                unsigned r[4];
                ldsm4t(r, sBb + (cur * B_STAGE + (kk * 16 + (lane & 15)) * BSTR
                                 + wn + nt2 * 16 + ((lane >> 4) & 1) * 8) * 2);
                b[2 * nt2][0] = r[0]; b[2 * nt2][1] = r[1];
                b[2 * nt2 + 1][0] = r[2]; b[2 * nt2 + 1][1] = r[3];
            }
            #pragma unroll
            for (int mt = 0; mt < 4; mt++) {
                unsigned a[4];
                ldsm4(a, sAb + (cur * A_STAGE + (wm + mt * 16 + (lane & 15)) * ASTR
                                + kk * 16 + ((lane >> 4) & 1) * 8) * 2);
                #pragma unroll
                for (int nt = 0; nt < 4; nt++) mma16816(acc[mt][nt], a, b[nt]);
            }
        }
        __syncthreads();
        cur++; if (cur >= NSTAGE) cur -= NSTAGE;
    }

    const int g = lane >> 2, tg = lane & 3;
    #pragma unroll
    for (int mt = 0; mt < 4; mt++) {
        const int r = m0 + wm + mt * 16 + g;
        #pragma unroll
        for (int nt = 0; nt < 4; nt++) {
            const int col = n0 + wn + nt * 8 + 2 * tg;
            const float2 bv = *(const float2*)&bias[col];
            float v00 = (acc[mt][nt][0] + bv.x) * scale;
            float v01 = (acc[mt][nt][1] + bv.y) * scale;
            float v10 = (acc[mt][nt][2] + bv.x) * scale;
            float v11 = (acc[mt][nt][3] + bv.y) * scale;
            if (MODE == 0) {
                *(float2*)&Cf[(size_t)r * DM + col]       = make_float2(v00, v01);
                *(float2*)&Cf[(size_t)(r + 8) * DM + col] = make_float2(v10, v11);
            } else {
                const int h = col >> 6, d = col & 63;
                int bb = r >> 11, ss = r & 2047;
                *(unsigned*)&Ch[(((size_t)(bb * NH + h) * SEQ) + ss) * HD + d] = pack2(v00, v01);
                bb = (r + 8) >> 11; ss = (r + 8) & 2047;
                *(unsigned*)&Ch[(((size_t)(bb * NH + h) * SEQ) + ss) * HD + d] = pack2(v10, v11);
            }
        }
    }
}

// ---------------------------------------------------------------------------
// FlashAttention-2, fp16 mma (128 thr, 64 q rows/block), exp2 softmax
// (Q pre-scaled by QSCALE at projection).
// ---------------------------------------------------------------------------
#define ATS 64
#define KSTR 72
#define KV_STAGE (ATS * KSTR)

__global__ __launch_bounds__(128) void attn_fa(
    const __half* __restrict__ Q, const __half* __restrict__ K,
    const __half* __restrict__ V, __half* __restrict__ Out)
{
    __shared__ __half sK[2 * KV_STAGE];
    __shared__ __half sV[2 * KV_STAGE];

    const int bh = blockIdx.y;
    const int q0 = blockIdx.x * ATS;
    const int tid = threadIdx.x;
    const int warp = tid >> 5, lane = tid & 31;
    const int g = lane >> 2, tg = lane & 3;
    const size_t base = (size_t)bh * SEQ * HD;
    const unsigned sKb = smem_u32(sK), sVb = smem_u32(sV);

    unsigned qf[4][4];
    {
        const int r0 = q0 + warp * 16;
        #pragma unroll
        for (int kk = 0; kk < 4; kk++) {
            const size_t i0 = base + (size_t)(r0 + g) * HD + kk * 16 + 2 * tg;
            const size_t i1 = base + (size_t)(r0 + g + 8) * HD + kk * 16 + 2 * tg;
            qf[kk][0] = *(const unsigned*)(Q + i0);
            qf[kk][1] = *(const unsigned*)(Q + i1);
            qf[kk][2] = *(const unsigned*)(Q + i0 + 8);
            qf[kk][3] = *(const unsigned*)(Q + i1 + 8);
        }
    }

    auto load_kv = [&](int st, int kv0) {
        #pragma unroll
        for (int c = 0; c < 4; c++) {
            int id = tid + c * 128;
            int row = id >> 3, col = (id & 7) * 8;
            size_t src = base + (size_t)(kv0 + row) * HD + col;
            unsigned off = (st * KV_STAGE + row * KSTR + col) * 2;
            cp16(sKb + off, K + src);
            cp16(sVb + off, V + src);
        }
    };

    float o[8][4];
    #pragma unroll
    for (int i = 0; i < 8; i++)
        #pragma unroll
        for (int j = 0; j < 4; j++) o[i][j] = 0.0f;
    float m0 = -1e30f, m1 = -1e30f, l0 = 0.0f, l1 = 0.0f;

    load_kv(0, 0);
    CP_COMMIT();

    const int NKV = SEQ / ATS;
    for (int it = 0; it < NKV; it++) {
        const int st = it & 1;
        if (it + 1 < NKV) { load_kv(st ^ 1, (it + 1) * ATS); CP_COMMIT(); CP_WAIT1(); }
        else              { CP_WAIT0(); }
        __syncthreads();

        float s[8][4];
        #pragma unroll
        for (int i = 0; i < 8; i++)
            #pragma unroll
            for (int j = 0; j < 4; j++) s[i][j] = 0.0f;

        #pragma unroll
        for (int kk = 0; kk < 4; kk++) {
            #pragma unroll
            for (int nt2 = 0; nt2 < 4; nt2++) {
                unsigned r[4];
                ldsm4(r, sKb + (st * KV_STAGE
                                + (nt2 * 16 + ((lane >> 4) << 3) + (lane & 7)) * KSTR
                                + kk * 16 + ((lane >> 3) & 1) * 8) * 2);
                mma16816(s[2 * nt2],     qf[kk], r);
                mma16816(s[2 * nt2 + 1], qf[kk], r + 2);
            }
        }

        // scores are already in log2 domain (QSCALE includes log2e)
        float mx0 = -1e30f, mx1 = -1e30f;
        #pragma unroll
        for (int nt = 0; nt < 8; nt++) {
            mx0 = fmaxf(mx0, fmaxf(s[nt][0], s[nt][1]));
            mx1 = fmaxf(mx1, fmaxf(s[nt][2], s[nt][3]));
        }
        mx0 = fmaxf(mx0, __shfl_xor_sync(~0u, mx0, 1));
        mx0 = fmaxf(mx0, __shfl_xor_sync(~0u, mx0, 2));
        mx1 = fmaxf(mx1, __shfl_xor_sync(~0u, mx1, 1));
        mx1 = fmaxf(mx1, __shfl_xor_sync(~0u, mx1, 2));
        const float mn0 = fmaxf(m0, mx0), mn1 = fmaxf(m1, mx1);
        const float c0 = ex2f(m0 - mn0), c1 = ex2f(m1 - mn1);
        m0 = mn0; m1 = mn1;

        float ps0 = 0.f, ps1 = 0.f;
        #pragma unroll
        for (int nt = 0; nt < 8; nt++) {
            s[nt][0] = ex2f(s[nt][0] - mn0);
            s[nt][1] = ex2f(s[nt][1] - mn0);
            s[nt][2] = ex2f(s[nt][2] - mn1);
            s[nt][3] = ex2f(s[nt][3] - mn1);
            ps0 += s[nt][0] + s[nt][1];
            ps1 += s[nt][2] + s[nt][3];
        }
        ps0 += __shfl_xor_sync(~0u, ps0, 1); ps0 += __shfl_xor_sync(~0u, ps0, 2);
        ps1 += __shfl_xor_sync(~0u, ps1, 1); ps1 += __shfl_xor_sync(~0u, ps1, 2);
        l0 = l0 * c0 + ps0;
        l1 = l1 * c1 + ps1;

        #pragma unroll
        for (int nt = 0; nt < 8; nt++) {
            o[nt][0] *= c0; o[nt][1] *= c0; o[nt][2] *= c1; o[nt][3] *= c1;
        }

        unsigned pa[4][4];
        #pragma unroll
        for (int kk = 0; kk < 4; kk++) {
            pa[kk][0] = pack2(s[2 * kk][0],     s[2 * kk][1]);
            pa[kk][1] = pack2(s[2 * kk][2],     s[2 * kk][3]);
            pa[kk][2] = pack2(s[2 * kk + 1][0], s[2 * kk + 1][1]);
            pa[kk][3] = pack2(s[2 * kk + 1][2], s[2 * kk + 1][3]);
        }

        #pragma unroll
        for (int kk = 0; kk < 4; kk++) {
            #pragma unroll
            for (int nt2 = 0; nt2 < 4; nt2++) {
                unsigned r[4];
                ldsm4t(r, sVb + (st * KV_STAGE + (kk * 16 + (lane & 15)) * KSTR
                                 + nt2 * 16 + ((lane >> 4) & 1) * 8) * 2);
                mma16816(o[2 * nt2],     pa[kk], r);
                mma16816(o[2 * nt2 + 1], pa[kk], r + 2);
            }
        }
        __syncthreads();
    }

    const float i0 = 1.0f / l0, i1 = 1.0f / l1;
    const int b = bh / NH, h = bh % NH;
    const size_t tok = (size_t)b * SEQ + q0 + warp * 16 + g;
    #pragma unroll
    for (int nt = 0; nt < 8; nt++) {
        const int col = h * HD + nt * 8 + 2 * tg;
        *(unsigned*)&Out[tok * DM + col]       = pack2(o[nt][0] * i0, o[nt][1] * i0);
        *(unsigned*)&Out[(tok + 8) * DM + col] = pack2(o[nt][2] * i1, o[nt][3] * i1);
    }
}

// ---------------------------------------------------------------------------
// Residual + LayerNorm
// ---------------------------------------------------------------------------
__global__ __launch_bounds__(256) void ln_kernel(
    const float* __restrict__ X, const float* __restrict__ P,
    const float* __restrict__ gamma, const float* __restrict__ beta,
    float* __restrict__ out)
{
    const int r = blockIdx.x, t = threadIdx.x;
    const float4 x4 = ((const float4*)(X + (size_t)r * DM))[t];
    const float4 p4 = ((const float4*)(P + (size_t)r * DM))[t];
    float v0 = x4.x + p4.x, v1 = x4.y + p4.y, v2 = x4.z + p4.z, v3 = x4.w + p4.w;

    __shared__ float red[8];
    __shared__ float s_mu, s_rstd;

    float s = v0 + v1 + v2 + v3;
    #pragma unroll
    for (int off = 16; off > 0; off >>= 1) s += __shfl_xor_sync(~0u, s, off);
    if ((t & 31) == 0) red[t >> 5] = s;
    __syncthreads();
    if (t == 0) {
        float tot = 0.f;
        #pragma unroll
        for (int i = 0; i < 8; i++) tot += red[i];
        s_mu = tot * (1.0f / DM);
    }
    __syncthreads();
    const float mu = s_mu;
    float d0 = v0 - mu, d1 = v1 - mu, d2 = v2 - mu, d3 = v3 - mu;
    float sq = d0 * d0 + d1 * d1 + d2 * d2 + d3 * d3;
    #pragma unroll
    for (int off = 16; off > 0; off >>= 1) sq += __shfl_xor_sync(~0u, sq, off);
    if ((t & 31) == 0) red[t >> 5] = sq;
    __syncthreads();
    if (t == 0) {
        float tot = 0.f;
        #pragma unroll
        for (int i = 0; i < 8; i++) tot += red[i];
        s_rstd = rsqrtf(tot * (1.0f / DM) + LN_EPS);
    }
    __syncthreads();
    const float rstd = s_rstd;

    const float4 g4 = ((const float4*)gamma)[t];
    const float4 b4 = ((const float4*)beta)[t];
    float4 o4;
    o4.x = d0 * rstd * g4.x + b4.x;
    o4.y = d1 * rstd * g4.y + b4.y;
    o4.z = d2 * rstd * g4.z + b4.z;
    o4.w = d3 * rstd * g4.w + b4.w;
    ((float4*)(out + (size_t)r * DM))[t] = o4;
}

// ---------------------------------------------------------------------------
// Launch
// ---------------------------------------------------------------------------
extern "C" void kernel_launch(void* const* d_in, const int* in_sizes, int n_in,
                              void* d_out, int out_size)
{
    const float* x     = (const float*)d_in[0];
    const float* Wq    = (const float*)d_in[1];
    const float* bq    = (const float*)d_in[2];
    const float* Wk    = (const float*)d_in[3];
    const float* bk    = (const float*)d_in[4];
    const float* Wv    = (const float*)d_in[5];
    const float* bv    = (const float*)d_in[6];
    const float* Wo    = (const float*)d_in[7];
    const float* bo    = (const float*)d_in[8];
    const float* gamma = (const float*)d_in[9];
    const float* beta  = (const float*)d_in[10];
    float* out = (float*)d_out;

    __half *hx, *hwq, *hwk, *hwv, *hwo, *q, *k, *v, *ah;
    float *proj;
    cudaGetSymbolAddress((void**)&hx,  g_hx);
    cudaGetSymbolAddress((void**)&hwq, g_hwq);
    cudaGetSymbolAddress((void**)&hwk, g_hwk);
    cudaGetSymbolAddress((void**)&hwv, g_hwv);
    cudaGetSymbolAddress((void**)&hwo, g_hwo);
    cudaGetSymbolAddress((void**)&q,   g_q);
    cudaGetSymbolAddress((void**)&k,   g_k);
    cudaGetSymbolAddress((void**)&v,   g_v);
    cudaGetSymbolAddress((void**)&ah,  g_ah);
    cudaGetSymbolAddress((void**)&proj, g_proj);

    cudaFuncSetAttribute(gemm_h<0>, cudaFuncAttributeMaxDynamicSharedMemorySize, GEMM_SMEM);
    cudaFuncSetAttribute(gemm_h<1>, cudaFuncAttributeMaxDynamicSharedMemorySize, GEMM_SMEM);

    cvt_kernel<<<NTOK * DM / 1024, 256>>>(x, hx, NTOK * DM);
    cvt_w_kernel<<<dim3(DM * DM / 1024, 4), 256>>>(Wq, Wk, Wv, Wo,
                                                   hwq, hwk, hwv, hwo);

    // Fused Q/K/V projections (z selects the matrix)
    gemm_h<1><<<dim3(DM / GBN, NTOK / GBM, 3), 256, GEMM_SMEM>>>(
        hx, hwq, hwk, hwv, bq, bk, bv, nullptr, q, k, v);

    attn_fa<<<dim3(SEQ / ATS, BATCH * NH), 128>>>(q, k, v, ah);

    gemm_h<0><<<dim3(DM / GBN, NTOK / GBM, 1), 256, GEMM_SMEM>>>(
        ah, hwo, nullptr, nullptr, bo, nullptr, nullptr, proj,
        nullptr, nullptr, nullptr);

    ln_kernel<<<NTOK, 256>>>(x, proj, gamma, beta, out);
}

// round 12
// speedup vs baseline: 1.1730x; 1.0222x over previous
#include <cuda_runtime.h>
#include <cuda_fp16.h>
#include <math.h>

#define BATCH 4
#define SEQ   2048
#define DM    1024
#define NH    16
#define HD    64
#define NTOK  (BATCH * SEQ)   // 8192
#define LN_EPS 1e-6f
// 1/sqrt(64) * log2(e) folded into Q projection so softmax can use raw exp2
#define QSCALE 0.18033688011112042f

// ---------------------------------------------------------------------------
// Device-global scratch
// ---------------------------------------------------------------------------
__device__ __half g_hx[NTOK * DM];
__device__ __half g_hwq[DM * DM], g_hwk[DM * DM], g_hwv[DM * DM], g_hwo[DM * DM];
__device__ __half g_q[NTOK * DM];             // [B,H,S,HD] (pre-scaled by QSCALE)
__device__ __half g_k[NTOK * DM];
__device__ __half g_v[NTOK * DM];
__device__ __half g_ah[NTOK * DM];            // attn out [B,S,DM]
__device__ float  g_proj[NTOK * DM];

// ---------------------------------------------------------------------------
// PTX helpers
// ---------------------------------------------------------------------------
__device__ __forceinline__ unsigned smem_u32(const void* p) {
    return (unsigned)__cvta_generic_to_shared(p);
}
__device__ __forceinline__ void ldsm4(unsigned* r, unsigned a) {
    asm volatile("ldmatrix.sync.aligned.m8n8.x4.shared.b16 {%0,%1,%2,%3},[%4];"
                 : "=r"(r[0]), "=r"(r[1]), "=r"(r[2]), "=r"(r[3]) : "r"(a));
}
__device__ __forceinline__ void ldsm4t(unsigned* r, unsigned a) {
    asm volatile("ldmatrix.sync.aligned.m8n8.x4.trans.shared.b16 {%0,%1,%2,%3},[%4];"
                 : "=r"(r[0]), "=r"(r[1]), "=r"(r[2]), "=r"(r[3]) : "r"(a));
}
__device__ __forceinline__ void mma16816(float* c, const unsigned* a, const unsigned* b) {
    asm volatile(
        "mma.sync.aligned.m16n8k16.row.col.f32.f16.f16.f32 "
        "{%0,%1,%2,%3},{%4,%5,%6,%7},{%8,%9},{%0,%1,%2,%3};"
        : "+f"(c[0]), "+f"(c[1]), "+f"(c[2]), "+f"(c[3])
        : "r"(a[0]), "r"(a[1]), "r"(a[2]), "r"(a[3]), "r"(b[0]), "r"(b[1]));
}
__device__ __forceinline__ void cp16(unsigned dst, const void* src) {
    asm volatile("cp.async.cg.shared.global [%0],[%1],16;" :: "r"(dst), "l"(src));
}
#define CP_COMMIT() asm volatile("cp.async.commit_group;")
#define CP_WAIT2()  asm volatile("cp.async.wait_group 2;")
#define CP_WAIT1()  asm volatile("cp.async.wait_group 1;")
#define CP_WAIT0()  asm volatile("cp.async.wait_group 0;")

__device__ __forceinline__ unsigned pack2(float x, float y) {
    __half2 h = __floats2half2_rn(x, y);
    return *reinterpret_cast<unsigned*>(&h);
}
__device__ __forceinline__ float ex2f(float x) {
    float r;
    asm("ex2.approx.ftz.f32 %0, %1;" : "=f"(r) : "f"(x));
    return r;
}
// pack two fp32 into half2 {lo, hi}
__device__ __forceinline__ unsigned cvth2(float lo, float hi) {
    unsigned d;
    asm("cvt.rn.f16x2.f32 %0, %1, %2;" : "=r"(d) : "f"(hi), "f"(lo));
    return d;
}
// 2^x on both halves
__device__ __forceinline__ unsigned ex2h2(unsigned a) {
    unsigned d;
    asm("ex2.approx.f16x2 %0, %1;" : "=r"(d) : "r"(a));
    return d;
}

// ---------------------------------------------------------------------------
// fp32 -> fp16 converts
// ---------------------------------------------------------------------------
__global__ __launch_bounds__(256) void cvt_kernel(
    const float* __restrict__ in, __half* __restrict__ out, int n)
{
    int i = (blockIdx.x * 256 + threadIdx.x) * 4;
    if (i >= n) return;
    float4 v = *(const float4*)(in + i);
    *(unsigned*)(out + i)     = pack2(v.x, v.y);
    *(unsigned*)(out + i + 2) = pack2(v.z, v.w);
}

__global__ __launch_bounds__(256) void cvt_w_kernel(
    const float* __restrict__ W0, const float* __restrict__ W1,
    const float* __restrict__ W2, const float* __restrict__ W3,
    __half* __restrict__ O0, __half* __restrict__ O1,
    __half* __restrict__ O2, __half* __restrict__ O3)
{
    const float* W; __half* O;
    switch (blockIdx.y) {
        case 0: W = W0; O = O0; break;
        case 1: W = W1; O = O1; break;
        case 2: W = W2; O = O2; break;
        default: W = W3; O = O3; break;
    }
    int i = (blockIdx.x * 256 + threadIdx.x) * 4;
    float4 v = *(const float4*)(W + i);
    *(unsigned*)(O + i)     = pack2(v.x, v.y);
    *(unsigned*)(O + i + 2) = pack2(v.z, v.w);
}

// ---------------------------------------------------------------------------
// fp16 mma GEMM. BM=BN=128, BK=64, 3-stage cp.async pipeline, 256 thr
// (8 warps 2x4), warp tile 64x32, dynamic smem 107.5KB (2 CTAs/SM).
// MODE 1: fused QKV (blockIdx.z selects). MODE 0: fp32 row-major out.
// ---------------------------------------------------------------------------
#define GBM 128
#define GBN 128
#define GBK 64
#define ASTR 72
#define BSTR 136
#define A_STAGE (GBM * ASTR)
#define B_STAGE (GBK * BSTR)
#define NSTAGE 3
#define GEMM_SMEM (NSTAGE * (A_STAGE + B_STAGE) * 2)  // 107520 B

template <int MODE>
__global__ __launch_bounds__(256) void gemm_h(
    const __half* __restrict__ Ag,
    const __half* __restrict__ W0g, const __half* __restrict__ W1g,
    const __half* __restrict__ W2g,
    const float* __restrict__ b0, const float* __restrict__ b1,
    const float* __restrict__ b2,
    float* __restrict__ Cf,
    __half* __restrict__ C0, __half* __restrict__ C1, __half* __restrict__ C2)
{
    extern __shared__ __half smem[];
    __half* sA = smem;
    __half* sB = smem + NSTAGE * A_STAGE;

    const __half* Wg; const float* bias; __half* Ch; float scale;
    if (MODE == 1) {
        switch (blockIdx.z) {
            case 0:  Wg = W0g; bias = b0; Ch = C0; scale = QSCALE; break;
            case 1:  Wg = W1g; bias = b1; Ch = C1; scale = 1.0f;   break;
            default: Wg = W2g; bias = b2; Ch = C2; scale = 1.0f;   break;
        }
    } else {
        Wg = W0g; bias = b0; Ch = nullptr; scale = 1.0f;
    }

    const int tid = threadIdx.x;
    const int lane = tid & 31, warp = tid >> 5;
    const int wm = (warp >> 2) * 64;
    const int wn = (warp & 3) * 32;
    const int m0 = blockIdx.y * GBM;
    const int n0 = blockIdx.x * GBN;
    const unsigned sAb = smem_u32(sA), sBb = smem_u32(sB);

    float acc[4][4][4];
    #pragma unroll
    for (int i = 0; i < 4; i++)
        #pragma unroll
        for (int j = 0; j < 4; j++)
            #pragma unroll
            for (int r = 0; r < 4; r++) acc[i][j][r] = 0.0f;

    auto load_stage = [&](int st, int k0) {
        #pragma unroll
        for (int c = 0; c < 4; c++) {
            int id = tid + c * 256;
            int row = id >> 3, col = (id & 7) * 8;
            cp16(sAb + (st * A_STAGE + row * ASTR + col) * 2,
                 Ag + (size_t)(m0 + row) * DM + k0 + col);
        }
        #pragma unroll
        for (int c = 0; c < 4; c++) {
            int id = tid + c * 256;
            int row = id >> 4, col = (id & 15) * 8;
            cp16(sBb + (st * B_STAGE + row * BSTR + col) * 2,
                 Wg + (size_t)(k0 + row) * DM + n0 + col);
        }
    };

    load_stage(0, 0);       CP_COMMIT();
    load_stage(1, GBK);     CP_COMMIT();

    const int NIT = DM / GBK;  // 16
    int cur = 0;
    for (int it = 0; it < NIT; it++) {
        if (it + 2 < NIT) {
            int nst = cur + 2; if (nst >= NSTAGE) nst -= NSTAGE;
            load_stage(nst, (it + 2) * GBK);
            CP_COMMIT();
            CP_WAIT2();
        } else if (it + 1 < NIT) { CP_WAIT1(); }
        else                     { CP_WAIT0(); }
        __syncthreads();

        #pragma unroll
        for (int kk = 0; kk < 4; kk++) {
            unsigned b[4][2];
            #pragma unroll
            for (int nt2 = 0; nt2 < 2; nt2++) {
                unsigned r[4];
                ldsm4t(r, sBb + (cur * B_STAGE + (kk * 16 + (lane & 15)) * BSTR
                                 + wn + nt2 * 16 + ((lane >> 4) & 1) * 8) * 2);
                b[2 * nt2][0] = r[0]; b[2 * nt2][1] = r[1];
                b[2 * nt2 + 1][0] = r[2]; b[2 * nt2 + 1][1] = r[3];
            }
            #pragma unroll
            for (int mt = 0; mt < 4; mt++) {
                unsigned a[4];
                ldsm4(a, sAb + (cur * A_STAGE + (wm + mt * 16 + (lane & 15)) * ASTR
                                + kk * 16 + ((lane >> 4) & 1) * 8) * 2);
                #pragma unroll
                for (int nt = 0; nt < 4; nt++) mma16816(acc[mt][nt], a, b[nt]);
            }
        }
        __syncthreads();
        cur++; if (cur >= NSTAGE) cur -= NSTAGE;
    }

    const int g = lane >> 2, tg = lane & 3;
    #pragma unroll
    for (int mt = 0; mt < 4; mt++) {
        const int r = m0 + wm + mt * 16 + g;
        #pragma unroll
        for (int nt = 0; nt < 4; nt++) {
            const int col = n0 + wn + nt * 8 + 2 * tg;
            const float2 bv = *(const float2*)&bias[col];
            float v00 = (acc[mt][nt][0] + bv.x) * scale;
            float v01 = (acc[mt][nt][1] + bv.y) * scale;
            float v10 = (acc[mt][nt][2] + bv.x) * scale;
            float v11 = (acc[mt][nt][3] + bv.y) * scale;
            if (MODE == 0) {
                *(float2*)&Cf[(size_t)r * DM + col]       = make_float2(v00, v01);
                *(float2*)&Cf[(size_t)(r + 8) * DM + col] = make_float2(v10, v11);
            } else {
                const int h = col >> 6, d = col & 63;
                int bb = r >> 11, ss = r & 2047;
                *(unsigned*)&Ch[(((size_t)(bb * NH + h) * SEQ) + ss) * HD + d] = pack2(v00, v01);
                bb = (r + 8) >> 11; ss = (r + 8) & 2047;
                *(unsigned*)&Ch[(((size_t)(bb * NH + h) * SEQ) + ss) * HD + d] = pack2(v10, v11);
            }
        }
    }
}

// ---------------------------------------------------------------------------
// FlashAttention-2, fp16 mma (128 thr, 64 q rows/block).
// exp2 softmax with ex2.approx.f16x2 producing P directly as half2 fragments;
// row-sums (l) accumulated via an extra ones-column mma; rescale skipped
// warp-uniformly when the running max is unchanged.
// ---------------------------------------------------------------------------
#define ATS 64
#define KSTR 72
#define KV_STAGE (ATS * KSTR)
#define ONES_H2 0x3C003C00u   // half2(1.0, 1.0)

__global__ __launch_bounds__(128) void attn_fa(
    const __half* __restrict__ Q, const __half* __restrict__ K,
    const __half* __restrict__ V, __half* __restrict__ Out)
{
    __shared__ __half sK[2 * KV_STAGE];
    __shared__ __half sV[2 * KV_STAGE];

    const int bh = blockIdx.y;
    const int q0 = blockIdx.x * ATS;
    const int tid = threadIdx.x;
    const int warp = tid >> 5, lane = tid & 31;
    const int g = lane >> 2, tg = lane & 3;
    const size_t base = (size_t)bh * SEQ * HD;
    const unsigned sKb = smem_u32(sK), sVb = smem_u32(sV);

    unsigned qf[4][4];
    {
        const int r0 = q0 + warp * 16;
        #pragma unroll
        for (int kk = 0; kk < 4; kk++) {
            const size_t i0 = base + (size_t)(r0 + g) * HD + kk * 16 + 2 * tg;
            const size_t i1 = base + (size_t)(r0 + g + 8) * HD + kk * 16 + 2 * tg;
            qf[kk][0] = *(const unsigned*)(Q + i0);
            qf[kk][1] = *(const unsigned*)(Q + i1);
            qf[kk][2] = *(const unsigned*)(Q + i0 + 8);
            qf[kk][3] = *(const unsigned*)(Q + i1 + 8);
        }
    }

    auto load_kv = [&](int st, int kv0) {
        #pragma unroll
        for (int c = 0; c < 4; c++) {
            int id = tid + c * 128;
            int row = id >> 3, col = (id & 7) * 8;
            size_t src = base + (size_t)(kv0 + row) * HD + col;
            unsigned off = (st * KV_STAGE + row * KSTR + col) * 2;
            cp16(sKb + off, K + src);
            cp16(sVb + off, V + src);
        }
    };

    float o[8][4];
    #pragma unroll
    for (int i = 0; i < 8; i++)
        #pragma unroll
        for (int j = 0; j < 4; j++) o[i][j] = 0.0f;
    float lacc[4] = {0.f, 0.f, 0.f, 0.f};     // row-sum accumulator (ones-mma)
    float m0 = -1e30f, m1 = -1e30f;
    const unsigned ones[2] = {ONES_H2, ONES_H2};

    load_kv(0, 0);
    CP_COMMIT();

    const int NKV = SEQ / ATS;
    for (int it = 0; it < NKV; it++) {
        const int st = it & 1;
        if (it + 1 < NKV) { load_kv(st ^ 1, (it + 1) * ATS); CP_COMMIT(); CP_WAIT1(); }
        else              { CP_WAIT0(); }
        __syncthreads();

        float s[8][4];
        #pragma unroll
        for (int i = 0; i < 8; i++)
            #pragma unroll
            for (int j = 0; j < 4; j++) s[i][j] = 0.0f;

        #pragma unroll
        for (int kk = 0; kk < 4; kk++) {
            #pragma unroll
            for (int nt2 = 0; nt2 < 4; nt2++) {
                unsigned r[4];
                ldsm4(r, sKb + (st * KV_STAGE
                                + (nt2 * 16 + ((lane >> 4) << 3) + (lane & 7)) * KSTR
                                + kk * 16 + ((lane >> 3) & 1) * 8) * 2);
                mma16816(s[2 * nt2],     qf[kk], r);
                mma16816(s[2 * nt2 + 1], qf[kk], r + 2);
            }
        }

        // scores are in log2 domain (QSCALE includes log2e)
        float mx0 = -1e30f, mx1 = -1e30f;
        #pragma unroll
        for (int nt = 0; nt < 8; nt++) {
            mx0 = fmaxf(mx0, fmaxf(s[nt][0], s[nt][1]));
            mx1 = fmaxf(mx1, fmaxf(s[nt][2], s[nt][3]));
        }
        mx0 = fmaxf(mx0, __shfl_xor_sync(~0u, mx0, 1));
        mx0 = fmaxf(mx0, __shfl_xor_sync(~0u, mx0, 2));
        mx1 = fmaxf(mx1, __shfl_xor_sync(~0u, mx1, 1));
        mx1 = fmaxf(mx1, __shfl_xor_sync(~0u, mx1, 2));
        const float mn0 = fmaxf(m0, mx0), mn1 = fmaxf(m1, mx1);

        // warp-uniform skip of the rescale when no row max changed
        const bool nochange = (mn0 == m0) & (mn1 == m1);
        if (!__all_sync(~0u, nochange)) {
            const float c0 = ex2f(m0 - mn0), c1 = ex2f(m1 - mn1);
            #pragma unroll
            for (int nt = 0; nt < 8; nt++) {
                o[nt][0] *= c0; o[nt][1] *= c0; o[nt][2] *= c1; o[nt][3] *= c1;
            }
            lacc[0] *= c0; lacc[1] *= c0; lacc[2] *= c1; lacc[3] *= c1;
        }
        m0 = mn0; m1 = mn1;

        // P fragments directly in half2 via packed exp2
        unsigned pa[4][4];
        #pragma unroll
        for (int kk = 0; kk < 4; kk++) {
            pa[kk][0] = ex2h2(cvth2(s[2 * kk][0] - mn0,     s[2 * kk][1] - mn0));
            pa[kk][1] = ex2h2(cvth2(s[2 * kk][2] - mn1,     s[2 * kk][3] - mn1));
            pa[kk][2] = ex2h2(cvth2(s[2 * kk + 1][0] - mn0, s[2 * kk + 1][1] - mn0));
            pa[kk][3] = ex2h2(cvth2(s[2 * kk + 1][2] - mn1, s[2 * kk + 1][3] - mn1));
        }

        // O += P @ V ; lacc += P @ ones (row sums)
        #pragma unroll
        for (int kk = 0; kk < 4; kk++) {
            mma16816(lacc, pa[kk], ones);
            #pragma unroll
            for (int nt2 = 0; nt2 < 4; nt2++) {
                unsigned r[4];
                ldsm4t(r, sVb + (st * KV_STAGE + (kk * 16 + (lane & 15)) * KSTR
                                 + nt2 * 16 + ((lane >> 4) & 1) * 8) * 2);
                mma16816(o[2 * nt2],     pa[kk], r);
                mma16816(o[2 * nt2 + 1], pa[kk], r + 2);
            }
        }
        __syncthreads();
    }

    const float i0 = 1.0f / lacc[0], i1 = 1.0f / lacc[2];
    const int b = bh / NH, h = bh % NH;
    const size_t tok = (size_t)b * SEQ + q0 + warp * 16 + g;
    #pragma unroll
    for (int nt = 0; nt < 8; nt++) {
        const int col = h * HD + nt * 8 + 2 * tg;
        *(unsigned*)&Out[tok * DM + col]       = pack2(o[nt][0] * i0, o[nt][1] * i0);
        *(unsigned*)&Out[(tok + 8) * DM + col] = pack2(o[nt][2] * i1, o[nt][3] * i1);
    }
}

// ---------------------------------------------------------------------------
// Residual + LayerNorm
// ---------------------------------------------------------------------------
__global__ __launch_bounds__(256) void ln_kernel(
    const float* __restrict__ X, const float* __restrict__ P,
    const float* __restrict__ gamma, const float* __restrict__ beta,
    float* __restrict__ out)
{
    const int r = blockIdx.x, t = threadIdx.x;
    const float4 x4 = ((const float4*)(X + (size_t)r * DM))[t];
    const float4 p4 = ((const float4*)(P + (size_t)r * DM))[t];
    float v0 = x4.x + p4.x, v1 = x4.y + p4.y, v2 = x4.z + p4.z, v3 = x4.w + p4.w;

    __shared__ float red[8];
    __shared__ float s_mu, s_rstd;

    float s = v0 + v1 + v2 + v3;
    #pragma unroll
    for (int off = 16; off > 0; off >>= 1) s += __shfl_xor_sync(~0u, s, off);
    if ((t & 31) == 0) red[t >> 5] = s;
    __syncthreads();
    if (t == 0) {
        float tot = 0.f;
        #pragma unroll
        for (int i = 0; i < 8; i++) tot += red[i];
        s_mu = tot * (1.0f / DM);
    }
    __syncthreads();
    const float mu = s_mu;
    float d0 = v0 - mu, d1 = v1 - mu, d2 = v2 - mu, d3 = v3 - mu;
    float sq = d0 * d0 + d1 * d1 + d2 * d2 + d3 * d3;
    #pragma unroll
    for (int off = 16; off > 0; off >>= 1) sq += __shfl_xor_sync(~0u, sq, off);
    if ((t & 31) == 0) red[t >> 5] = sq;
    __syncthreads();
    if (t == 0) {
        float tot = 0.f;
        #pragma unroll
        for (int i = 0; i < 8; i++) tot += red[i];
        s_rstd = rsqrtf(tot * (1.0f / DM) + LN_EPS);
    }
    __syncthreads();
    const float rstd = s_rstd;

    const float4 g4 = ((const float4*)gamma)[t];
    const float4 b4 = ((const float4*)beta)[t];
    float4 o4;
    o4.x = d0 * rstd * g4.x + b4.x;
    o4.y = d1 * rstd * g4.y + b4.y;
    o4.z = d2 * rstd * g4.z + b4.z;
    o4.w = d3 * rstd * g4.w + b4.w;
    ((float4*)(out + (size_t)r * DM))[t] = o4;
}

// ---------------------------------------------------------------------------
// Launch
// ---------------------------------------------------------------------------
extern "C" void kernel_launch(void* const* d_in, const int* in_sizes, int n_in,
                              void* d_out, int out_size)
{
    const float* x     = (const float*)d_in[0];
    const float* Wq    = (const float*)d_in[1];
    const float* bq    = (const float*)d_in[2];
    const float* Wk    = (const float*)d_in[3];
    const float* bk    = (const float*)d_in[4];
    const float* Wv    = (const float*)d_in[5];
    const float* bv    = (const float*)d_in[6];
    const float* Wo    = (const float*)d_in[7];
    const float* bo    = (const float*)d_in[8];
    const float* gamma = (const float*)d_in[9];
    const float* beta  = (const float*)d_in[10];
    float* out = (float*)d_out;

    __half *hx, *hwq, *hwk, *hwv, *hwo, *q, *k, *v, *ah;
    float *proj;
    cudaGetSymbolAddress((void**)&hx,  g_hx);
    cudaGetSymbolAddress((void**)&hwq, g_hwq);
    cudaGetSymbolAddress((void**)&hwk, g_hwk);
    cudaGetSymbolAddress((void**)&hwv, g_hwv);
    cudaGetSymbolAddress((void**)&hwo, g_hwo);
    cudaGetSymbolAddress((void**)&q,   g_q);
    cudaGetSymbolAddress((void**)&k,   g_k);
    cudaGetSymbolAddress((void**)&v,   g_v);
    cudaGetSymbolAddress((void**)&ah,  g_ah);
    cudaGetSymbolAddress((void**)&proj, g_proj);

    cudaFuncSetAttribute(gemm_h<0>, cudaFuncAttributeMaxDynamicSharedMemorySize, GEMM_SMEM);
    cudaFuncSetAttribute(gemm_h<1>, cudaFuncAttributeMaxDynamicSharedMemorySize, GEMM_SMEM);

    cvt_kernel<<<NTOK * DM / 1024, 256>>>(x, hx, NTOK * DM);
    cvt_w_kernel<<<dim3(DM * DM / 1024, 4), 256>>>(Wq, Wk, Wv, Wo,
                                                   hwq, hwk, hwv, hwo);

    gemm_h<1><<<dim3(DM / GBN, NTOK / GBM, 3), 256, GEMM_SMEM>>>(
        hx, hwq, hwk, hwv, bq, bk, bv, nullptr, q, k, v);

    attn_fa<<<dim3(SEQ / ATS, BATCH * NH), 128>>>(q, k, v, ah);

    gemm_h<0><<<dim3(DM / GBN, NTOK / GBM, 1), 256, GEMM_SMEM>>>(
        ah, hwo, nullptr, nullptr, bo, nullptr, nullptr, proj,
        nullptr, nullptr, nullptr);

    ln_kernel<<<NTOK, 256>>>(x, proj, gamma, beta, out);
}

// round 13
// speedup vs baseline: 1.1952x; 1.0189x over previous
#include <cuda_runtime.h>
#include <cuda_fp16.h>
#include <math.h>

#define BATCH 4
#define SEQ   2048
#define DM    1024
#define NH    16
#define HD    64
#define NTOK  (BATCH * SEQ)   // 8192
#define LN_EPS 1e-6f
// 1/sqrt(64) * log2(e) folded into Q projection so softmax can use raw exp2
#define QSCALE 0.18033688011112042f

// ---------------------------------------------------------------------------
// Device-global scratch
// ---------------------------------------------------------------------------
__device__ __half g_hx[NTOK * DM];
__device__ __half g_hwq[DM * DM], g_hwk[DM * DM], g_hwv[DM * DM], g_hwo[DM * DM];
__device__ __half g_q[NTOK * DM];             // [B,H,S,HD] (pre-scaled by QSCALE)
__device__ __half g_k[NTOK * DM];
__device__ __half g_v[NTOK * DM];
__device__ __half g_ah[NTOK * DM];            // attn out [B,S,DM]
__device__ float  g_proj[NTOK * DM];

// ---------------------------------------------------------------------------
// PTX helpers
// ---------------------------------------------------------------------------
__device__ __forceinline__ unsigned smem_u32(const void* p) {
    return (unsigned)__cvta_generic_to_shared(p);
}
__device__ __forceinline__ void ldsm4(unsigned* r, unsigned a) {
    asm volatile("ldmatrix.sync.aligned.m8n8.x4.shared.b16 {%0,%1,%2,%3},[%4];"
                 : "=r"(r[0]), "=r"(r[1]), "=r"(r[2]), "=r"(r[3]) : "r"(a));
}
__device__ __forceinline__ void ldsm4t(unsigned* r, unsigned a) {
    asm volatile("ldmatrix.sync.aligned.m8n8.x4.trans.shared.b16 {%0,%1,%2,%3},[%4];"
                 : "=r"(r[0]), "=r"(r[1]), "=r"(r[2]), "=r"(r[3]) : "r"(a));
}
__device__ __forceinline__ void mma16816(float* c, const unsigned* a, const unsigned* b) {
    asm volatile(
        "mma.sync.aligned.m16n8k16.row.col.f32.f16.f16.f32 "
        "{%0,%1,%2,%3},{%4,%5,%6,%7},{%8,%9},{%0,%1,%2,%3};"
        : "+f"(c[0]), "+f"(c[1]), "+f"(c[2]), "+f"(c[3])
        : "r"(a[0]), "r"(a[1]), "r"(a[2]), "r"(a[3]), "r"(b[0]), "r"(b[1]));
}
__device__ __forceinline__ void cp16(unsigned dst, const void* src) {
    asm volatile("cp.async.cg.shared.global [%0],[%1],16;" :: "r"(dst), "l"(src));
}
#define CP_COMMIT() asm volatile("cp.async.commit_group;")
#define CP_WAIT2()  asm volatile("cp.async.wait_group 2;")
#define CP_WAIT1()  asm volatile("cp.async.wait_group 1;")
#define CP_WAIT0()  asm volatile("cp.async.wait_group 0;")

__device__ __forceinline__ unsigned pack2(float x, float y) {
    __half2 h = __floats2half2_rn(x, y);
    return *reinterpret_cast<unsigned*>(&h);
}
__device__ __forceinline__ float ex2f(float x) {
    float r;
    asm("ex2.approx.ftz.f32 %0, %1;" : "=f"(r) : "f"(x));
    return r;
}
__device__ __forceinline__ unsigned cvth2(float lo, float hi) {
    unsigned d;
    asm("cvt.rn.f16x2.f32 %0, %1, %2;" : "=r"(d) : "f"(hi), "f"(lo));
    return d;
}
__device__ __forceinline__ unsigned ex2h2(unsigned a) {
    unsigned d;
    asm("ex2.approx.f16x2 %0, %1;" : "=r"(d) : "r"(a));
    return d;
}

// ---------------------------------------------------------------------------
// fp32 -> fp16 converts
// ---------------------------------------------------------------------------
__global__ __launch_bounds__(256) void cvt_kernel(
    const float* __restrict__ in, __half* __restrict__ out, int n)
{
    int i = (blockIdx.x * 256 + threadIdx.x) * 4;
    if (i >= n) return;
    float4 v = *(const float4*)(in + i);
    *(unsigned*)(out + i)     = pack2(v.x, v.y);
    *(unsigned*)(out + i + 2) = pack2(v.z, v.w);
}

__global__ __launch_bounds__(256) void cvt_w_kernel(
    const float* __restrict__ W0, const float* __restrict__ W1,
    const float* __restrict__ W2, const float* __restrict__ W3,
    __half* __restrict__ O0, __half* __restrict__ O1,
    __half* __restrict__ O2, __half* __restrict__ O3)
{
    const float* W; __half* O;
    switch (blockIdx.y) {
        case 0: W = W0; O = O0; break;
        case 1: W = W1; O = O1; break;
        case 2: W = W2; O = O2; break;
        default: W = W3; O = O3; break;
    }
    int i = (blockIdx.x * 256 + threadIdx.x) * 4;
    float4 v = *(const float4*)(W + i);
    *(unsigned*)(O + i)     = pack2(v.x, v.y);
    *(unsigned*)(O + i + 2) = pack2(v.z, v.w);
}

// ---------------------------------------------------------------------------
// fp16 mma GEMM. BM=BN=128, BK=64, 3-stage cp.async pipeline, 256 thr
// (8 warps 2x4), warp tile 64x32, dynamic smem 107.5KB (2 CTAs/SM).
// MODE 1: fused QKV (blockIdx.z selects). MODE 0: fp32 row-major out.
// ---------------------------------------------------------------------------
#define GBM 128
#define GBN 128
#define GBK 64
#define ASTR 72
#define BSTR 136
#define A_STAGE (GBM * ASTR)
#define B_STAGE (GBK * BSTR)
#define NSTAGE 3
#define GEMM_SMEM (NSTAGE * (A_STAGE + B_STAGE) * 2)  // 107520 B

template <int MODE>
__global__ __launch_bounds__(256) void gemm_h(
    const __half* __restrict__ Ag,
    const __half* __restrict__ W0g, const __half* __restrict__ W1g,
    const __half* __restrict__ W2g,
    const float* __restrict__ b0, const float* __restrict__ b1,
    const float* __restrict__ b2,
    float* __restrict__ Cf,
    __half* __restrict__ C0, __half* __restrict__ C1, __half* __restrict__ C2)
{
    extern __shared__ __half smem[];
    __half* sA = smem;
    __half* sB = smem + NSTAGE * A_STAGE;

    const __half* Wg; const float* bias; __half* Ch; float scale;
    if (MODE == 1) {
        switch (blockIdx.z) {
            case 0:  Wg = W0g; bias = b0; Ch = C0; scale = QSCALE; break;
            case 1:  Wg = W1g; bias = b1; Ch = C1; scale = 1.0f;   break;
            default: Wg = W2g; bias = b2; Ch = C2; scale = 1.0f;   break;
        }
    } else {
        Wg = W0g; bias = b0; Ch = nullptr; scale = 1.0f;
    }

    const int tid = threadIdx.x;
    const int lane = tid & 31, warp = tid >> 5;
    const int wm = (warp >> 2) * 64;
    const int wn = (warp & 3) * 32;
    const int m0 = blockIdx.y * GBM;
    const int n0 = blockIdx.x * GBN;
    const unsigned sAb = smem_u32(sA), sBb = smem_u32(sB);

    float acc[4][4][4];
    #pragma unroll
    for (int i = 0; i < 4; i++)
        #pragma unroll
        for (int j = 0; j < 4; j++)
            #pragma unroll
            for (int r = 0; r < 4; r++) acc[i][j][r] = 0.0f;

    auto load_stage = [&](int st, int k0) {
        #pragma unroll
        for (int c = 0; c < 4; c++) {
            int id = tid + c * 256;
            int row = id >> 3, col = (id & 7) * 8;
            cp16(sAb + (st * A_STAGE + row * ASTR + col) * 2,
                 Ag + (size_t)(m0 + row) * DM + k0 + col);
        }
        #pragma unroll
        for (int c = 0; c < 4; c++) {
            int id = tid + c * 256;
            int row = id >> 4, col = (id & 15) * 8;
            cp16(sBb + (st * B_STAGE + row * BSTR + col) * 2,
                 Wg + (size_t)(k0 + row) * DM + n0 + col);
        }
    };

    load_stage(0, 0);       CP_COMMIT();
    load_stage(1, GBK);     CP_COMMIT();

    const int NIT = DM / GBK;  // 16
    int cur = 0;
    for (int it = 0; it < NIT; it++) {
        if (it + 2 < NIT) {
            int nst = cur + 2; if (nst >= NSTAGE) nst -= NSTAGE;
            load_stage(nst, (it + 2) * GBK);
            CP_COMMIT();
            CP_WAIT2();
        } else if (it + 1 < NIT) { CP_WAIT1(); }
        else                     { CP_WAIT0(); }
        __syncthreads();

        #pragma unroll
        for (int kk = 0; kk < 4; kk++) {
            unsigned b[4][2];
            #pragma unroll
            for (int nt2 = 0; nt2 < 2; nt2++) {
                unsigned r[4];
                ldsm4t(r, sBb + (cur * B_STAGE + (kk * 16 + (lane & 15)) * BSTR
                                 + wn + nt2 * 16 + ((lane >> 4) & 1) * 8) * 2);
                b[2 * nt2][0] = r[0]; b[2 * nt2][1] = r[1];
                b[2 * nt2 + 1][0] = r[2]; b[2 * nt2 + 1][1] = r[3];
            }
            #pragma unroll
            for (int mt = 0; mt < 4; mt++) {
                unsigned a[4];
                ldsm4(a, sAb + (cur * A_STAGE + (wm + mt * 16 + (lane & 15)) * ASTR
                                + kk * 16 + ((lane >> 4) & 1) * 8) * 2);
                #pragma unroll
                for (int nt = 0; nt < 4; nt++) mma16816(acc[mt][nt], a, b[nt]);
            }
        }
        __syncthreads();
        cur++; if (cur >= NSTAGE) cur -= NSTAGE;
    }

    const int g = lane >> 2, tg = lane & 3;
    #pragma unroll
    for (int mt = 0; mt < 4; mt++) {
        const int r = m0 + wm + mt * 16 + g;
        #pragma unroll
        for (int nt = 0; nt < 4; nt++) {
            const int col = n0 + wn + nt * 8 + 2 * tg;
            const float2 bv = *(const float2*)&bias[col];
            float v00 = (acc[mt][nt][0] + bv.x) * scale;
            float v01 = (acc[mt][nt][1] + bv.y) * scale;
            float v10 = (acc[mt][nt][2] + bv.x) * scale;
            float v11 = (acc[mt][nt][3] + bv.y) * scale;
            if (MODE == 0) {
                *(float2*)&Cf[(size_t)r * DM + col]       = make_float2(v00, v01);
                *(float2*)&Cf[(size_t)(r + 8) * DM + col] = make_float2(v10, v11);
            } else {
                const int h = col >> 6, d = col & 63;
                int bb = r >> 11, ss = r & 2047;
                *(unsigned*)&Ch[(((size_t)(bb * NH + h) * SEQ) + ss) * HD + d] = pack2(v00, v01);
                bb = (r + 8) >> 11; ss = (r + 8) & 2047;
                *(unsigned*)&Ch[(((size_t)(bb * NH + h) * SEQ) + ss) * HD + d] = pack2(v10, v11);
            }
        }
    }
}

// ---------------------------------------------------------------------------
// FlashAttention-2, fp16 mma. 128 thr (4 warps), 32 q rows PER WARP
// (two 16-row subtiles sharing every K/V ldmatrix fragment -> ldsm/mma
// halved). 128 q rows per block. exp2 softmax (f16x2), ones-mma row sums,
// per-subtile skip-rescale.
// ---------------------------------------------------------------------------
#define ATS 64
#define QW  32                  // q rows per warp
#define QBLK 128                // q rows per block
#define KSTR 72
#define KV_STAGE (ATS * KSTR)
#define ONES_H2 0x3C003C00u

__global__ __launch_bounds__(128) void attn_fa(
    const __half* __restrict__ Q, const __half* __restrict__ K,
    const __half* __restrict__ V, __half* __restrict__ Out)
{
    __shared__ __half sK[2 * KV_STAGE];
    __shared__ __half sV[2 * KV_STAGE];

    const int bh = blockIdx.y;
    const int q0 = blockIdx.x * QBLK;
    const int tid = threadIdx.x;
    const int warp = tid >> 5, lane = tid & 31;
    const int g = lane >> 2, tg = lane & 3;
    const size_t base = (size_t)bh * SEQ * HD;
    const unsigned sKb = smem_u32(sK), sVb = smem_u32(sV);

    // Q fragments for two 16-row subtiles
    unsigned qf[2][4][4];
    #pragma unroll
    for (int u = 0; u < 2; u++) {
        const int r0 = q0 + warp * QW + u * 16;
        #pragma unroll
        for (int kk = 0; kk < 4; kk++) {
            const size_t i0 = base + (size_t)(r0 + g) * HD + kk * 16 + 2 * tg;
            const size_t i1 = base + (size_t)(r0 + g + 8) * HD + kk * 16 + 2 * tg;
            qf[u][kk][0] = *(const unsigned*)(Q + i0);
            qf[u][kk][1] = *(const unsigned*)(Q + i1);
            qf[u][kk][2] = *(const unsigned*)(Q + i0 + 8);
            qf[u][kk][3] = *(const unsigned*)(Q + i1 + 8);
        }
    }

    auto load_kv = [&](int st, int kv0) {
        #pragma unroll
        for (int c = 0; c < 4; c++) {
            int id = tid + c * 128;
            int row = id >> 3, col = (id & 7) * 8;
            size_t src = base + (size_t)(kv0 + row) * HD + col;
            unsigned off = (st * KV_STAGE + row * KSTR + col) * 2;
            cp16(sKb + off, K + src);
            cp16(sVb + off, V + src);
        }
    };

    float o[2][8][4];
    #pragma unroll
    for (int u = 0; u < 2; u++)
        #pragma unroll
        for (int i = 0; i < 8; i++)
            #pragma unroll
            for (int j = 0; j < 4; j++) o[u][i][j] = 0.0f;
    float lacc[2][4] = {{0.f,0.f,0.f,0.f},{0.f,0.f,0.f,0.f}};
    float m0[2] = {-1e30f, -1e30f}, m1[2] = {-1e30f, -1e30f};
    const unsigned ones[2] = {ONES_H2, ONES_H2};

    // loop-invariant ldsm lane addressing
    const unsigned kladdr = ((lane >> 4) << 3 | (lane & 7)) * KSTR * 2
                            + (((lane >> 3) & 1) * 8) * 2;
    const unsigned vladdr = ((lane & 15)) * KSTR * 2 + (((lane >> 4) & 1) * 8) * 2;

    load_kv(0, 0);
    CP_COMMIT();

    const int NKV = SEQ / ATS;
    for (int it = 0; it < NKV; it++) {
        const int st = it & 1;
        if (it + 1 < NKV) { load_kv(st ^ 1, (it + 1) * ATS); CP_COMMIT(); CP_WAIT1(); }
        else              { CP_WAIT0(); }
        __syncthreads();
        const unsigned kbase = sKb + st * KV_STAGE * 2;
        const unsigned vbase = sVb + st * KV_STAGE * 2;

        // ---- S = Q @ K^T for both subtiles, sharing each K fragment
        float s[2][8][4];
        #pragma unroll
        for (int u = 0; u < 2; u++)
            #pragma unroll
            for (int i = 0; i < 8; i++)
                #pragma unroll
                for (int j = 0; j < 4; j++) s[u][i][j] = 0.0f;

        #pragma unroll
        for (int kk = 0; kk < 4; kk++) {
            #pragma unroll
            for (int nt2 = 0; nt2 < 4; nt2++) {
                unsigned r[4];
                ldsm4(r, kbase + kladdr + (nt2 * 16 * KSTR + kk * 16) * 2);
                #pragma unroll
                for (int u = 0; u < 2; u++) {
                    mma16816(s[u][2 * nt2],     qf[u][kk], r);
                    mma16816(s[u][2 * nt2 + 1], qf[u][kk], r + 2);
                }
            }
        }

        // ---- softmax per subtile (log2 domain)
        unsigned pa[2][4][4];
        #pragma unroll
        for (int u = 0; u < 2; u++) {
            float mx0 = -1e30f, mx1 = -1e30f;
            #pragma unroll
            for (int nt = 0; nt < 8; nt++) {
                mx0 = fmaxf(mx0, fmaxf(s[u][nt][0], s[u][nt][1]));
                mx1 = fmaxf(mx1, fmaxf(s[u][nt][2], s[u][nt][3]));
            }
            mx0 = fmaxf(mx0, __shfl_xor_sync(~0u, mx0, 1));
            mx0 = fmaxf(mx0, __shfl_xor_sync(~0u, mx0, 2));
            mx1 = fmaxf(mx1, __shfl_xor_sync(~0u, mx1, 1));
            mx1 = fmaxf(mx1, __shfl_xor_sync(~0u, mx1, 2));
            const float mn0 = fmaxf(m0[u], mx0), mn1 = fmaxf(m1[u], mx1);

            const bool nochange = (mn0 == m0[u]) & (mn1 == m1[u]);
            if (!__all_sync(~0u, nochange)) {
                const float c0 = ex2f(m0[u] - mn0), c1 = ex2f(m1[u] - mn1);
                #pragma unroll
                for (int nt = 0; nt < 8; nt++) {
                    o[u][nt][0] *= c0; o[u][nt][1] *= c0;
                    o[u][nt][2] *= c1; o[u][nt][3] *= c1;
                }
                lacc[u][0] *= c0; lacc[u][1] *= c0;
                lacc[u][2] *= c1; lacc[u][3] *= c1;
            }
            m0[u] = mn0; m1[u] = mn1;

            #pragma unroll
            for (int kk = 0; kk < 4; kk++) {
                pa[u][kk][0] = ex2h2(cvth2(s[u][2 * kk][0] - mn0,     s[u][2 * kk][1] - mn0));
                pa[u][kk][1] = ex2h2(cvth2(s[u][2 * kk][2] - mn1,     s[u][2 * kk][3] - mn1));
                pa[u][kk][2] = ex2h2(cvth2(s[u][2 * kk + 1][0] - mn0, s[u][2 * kk + 1][1] - mn0));
                pa[u][kk][3] = ex2h2(cvth2(s[u][2 * kk + 1][2] - mn1, s[u][2 * kk + 1][3] - mn1));
            }
        }

        // ---- O += P @ V ; lacc += P @ ones — sharing each V fragment
        #pragma unroll
        for (int kk = 0; kk < 4; kk++) {
            mma16816(lacc[0], pa[0][kk], ones);
            mma16816(lacc[1], pa[1][kk], ones);
            #pragma unroll
            for (int nt2 = 0; nt2 < 4; nt2++) {
                unsigned r[4];
                ldsm4t(r, vbase + vladdr + (kk * 16 * KSTR + nt2 * 16) * 2);
                #pragma unroll
                for (int u = 0; u < 2; u++) {
                    mma16816(o[u][2 * nt2],     pa[u][kk], r);
                    mma16816(o[u][2 * nt2 + 1], pa[u][kk], r + 2);
                }
            }
        }
        __syncthreads();
    }

    const int b = bh / NH, h = bh % NH;
    #pragma unroll
    for (int u = 0; u < 2; u++) {
        const float i0 = 1.0f / lacc[u][0], i1 = 1.0f / lacc[u][2];
        const size_t tok = (size_t)b * SEQ + q0 + warp * QW + u * 16 + g;
        #pragma unroll
        for (int nt = 0; nt < 8; nt++) {
            const int col = h * HD + nt * 8 + 2 * tg;
            *(unsigned*)&Out[tok * DM + col]       = pack2(o[u][nt][0] * i0, o[u][nt][1] * i0);
            *(unsigned*)&Out[(tok + 8) * DM + col] = pack2(o[u][nt][2] * i1, o[u][nt][3] * i1);
        }
    }
}

// ---------------------------------------------------------------------------
// Residual + LayerNorm
// ---------------------------------------------------------------------------
__global__ __launch_bounds__(256) void ln_kernel(
    const float* __restrict__ X, const float* __restrict__ P,
    const float* __restrict__ gamma, const float* __restrict__ beta,
    float* __restrict__ out)
{
    const int r = blockIdx.x, t = threadIdx.x;
    const float4 x4 = ((const float4*)(X + (size_t)r * DM))[t];
    const float4 p4 = ((const float4*)(P + (size_t)r * DM))[t];
    float v0 = x4.x + p4.x, v1 = x4.y + p4.y, v2 = x4.z + p4.z, v3 = x4.w + p4.w;

    __shared__ float red[8];
    __shared__ float s_mu, s_rstd;

    float s = v0 + v1 + v2 + v3;
    #pragma unroll
    for (int off = 16; off > 0; off >>= 1) s += __shfl_xor_sync(~0u, s, off);
    if ((t & 31) == 0) red[t >> 5] = s;
    __syncthreads();
    if (t == 0) {
        float tot = 0.f;
        #pragma unroll
        for (int i = 0; i < 8; i++) tot += red[i];
        s_mu = tot * (1.0f / DM);
    }
    __syncthreads();
    const float mu = s_mu;
    float d0 = v0 - mu, d1 = v1 - mu, d2 = v2 - mu, d3 = v3 - mu;
    float sq = d0 * d0 + d1 * d1 + d2 * d2 + d3 * d3;
    #pragma unroll
    for (int off = 16; off > 0; off >>= 1) sq += __shfl_xor_sync(~0u, sq, off);
    if ((t & 31) == 0) red[t >> 5] = sq;
    __syncthreads();
    if (t == 0) {
        float tot = 0.f;
        #pragma unroll
        for (int i = 0; i < 8; i++) tot += red[i];
        s_rstd = rsqrtf(tot * (1.0f / DM) + LN_EPS);
    }
    __syncthreads();
    const float rstd = s_rstd;

    const float4 g4 = ((const float4*)gamma)[t];
    const float4 b4 = ((const float4*)beta)[t];
    float4 o4;
    o4.x = d0 * rstd * g4.x + b4.x;
    o4.y = d1 * rstd * g4.y + b4.y;
    o4.z = d2 * rstd * g4.z + b4.z;
    o4.w = d3 * rstd * g4.w + b4.w;
    ((float4*)(out + (size_t)r * DM))[t] = o4;
}

// ---------------------------------------------------------------------------
// Launch
// ---------------------------------------------------------------------------
extern "C" void kernel_launch(void* const* d_in, const int* in_sizes, int n_in,
                              void* d_out, int out_size)
{
    const float* x     = (const float*)d_in[0];
    const float* Wq    = (const float*)d_in[1];
    const float* bq    = (const float*)d_in[2];
    const float* Wk    = (const float*)d_in[3];
    const float* bk    = (const float*)d_in[4];
    const float* Wv    = (const float*)d_in[5];
    const float* bv    = (const float*)d_in[6];
    const float* Wo    = (const float*)d_in[7];
    const float* bo    = (const float*)d_in[8];
    const float* gamma = (const float*)d_in[9];
    const float* beta  = (const float*)d_in[10];
    float* out = (float*)d_out;

    __half *hx, *hwq, *hwk, *hwv, *hwo, *q, *k, *v, *ah;
    float *proj;
    cudaGetSymbolAddress((void**)&hx,  g_hx);
    cudaGetSymbolAddress((void**)&hwq, g_hwq);
    cudaGetSymbolAddress((void**)&hwk, g_hwk);
    cudaGetSymbolAddress((void**)&hwv, g_hwv);
    cudaGetSymbolAddress((void**)&hwo, g_hwo);
    cudaGetSymbolAddress((void**)&q,   g_q);
    cudaGetSymbolAddress((void**)&k,   g_k);
    cudaGetSymbolAddress((void**)&v,   g_v);
    cudaGetSymbolAddress((void**)&ah,  g_ah);
    cudaGetSymbolAddress((void**)&proj, g_proj);

    cudaFuncSetAttribute(gemm_h<0>, cudaFuncAttributeMaxDynamicSharedMemorySize, GEMM_SMEM);
    cudaFuncSetAttribute(gemm_h<1>, cudaFuncAttributeMaxDynamicSharedMemorySize, GEMM_SMEM);

    cvt_kernel<<<NTOK * DM / 1024, 256>>>(x, hx, NTOK * DM);
    cvt_w_kernel<<<dim3(DM * DM / 1024, 4), 256>>>(Wq, Wk, Wv, Wo,
                                                   hwq, hwk, hwv, hwo);

    gemm_h<1><<<dim3(DM / GBN, NTOK / GBM, 3), 256, GEMM_SMEM>>>(
        hx, hwq, hwk, hwv, bq, bk, bv, nullptr, q, k, v);

    attn_fa<<<dim3(SEQ / QBLK, BATCH * NH), 128>>>(q, k, v, ah);

    gemm_h<0><<<dim3(DM / GBN, NTOK / GBM, 1), 256, GEMM_SMEM>>>(
        ah, hwo, nullptr, nullptr, bo, nullptr, nullptr, proj,
        nullptr, nullptr, nullptr);

    ln_kernel<<<NTOK, 256>>>(x, proj, gamma, beta, out);
}

// round 14
// speedup vs baseline: 1.2162x; 1.0175x over previous
#include <cuda_runtime.h>
#include <cuda_fp16.h>
#include <math.h>

#define BATCH 4
#define SEQ   2048
#define DM    1024
#define NH    16
#define HD    64
#define NTOK  (BATCH * SEQ)   // 8192
#define LN_EPS 1e-6f
// 1/sqrt(64) * log2(e) folded into Q projection so softmax can use raw exp2
#define QSCALE 0.18033688011112042f

// ---------------------------------------------------------------------------
// Device-global scratch
// ---------------------------------------------------------------------------
__device__ __half g_hx[NTOK * DM];
__device__ __half g_hwq[DM * DM], g_hwk[DM * DM], g_hwv[DM * DM], g_hwo[DM * DM];
__device__ __half g_q[NTOK * DM];             // [B,H,S,HD] (pre-scaled by QSCALE)
__device__ __half g_k[NTOK * DM];
__device__ __half g_v[NTOK * DM];
__device__ __half g_ah[NTOK * DM];            // attn out [B,S,DM]
__device__ float  g_proj[NTOK * DM];

// ---------------------------------------------------------------------------
// PTX helpers
// ---------------------------------------------------------------------------
__device__ __forceinline__ unsigned smem_u32(const void* p) {
    return (unsigned)__cvta_generic_to_shared(p);
}
__device__ __forceinline__ void ldsm4(unsigned* r, unsigned a) {
    asm volatile("ldmatrix.sync.aligned.m8n8.x4.shared.b16 {%0,%1,%2,%3},[%4];"
                 : "=r"(r[0]), "=r"(r[1]), "=r"(r[2]), "=r"(r[3]) : "r"(a));
}
__device__ __forceinline__ void ldsm4t(unsigned* r, unsigned a) {
    asm volatile("ldmatrix.sync.aligned.m8n8.x4.trans.shared.b16 {%0,%1,%2,%3},[%4];"
                 : "=r"(r[0]), "=r"(r[1]), "=r"(r[2]), "=r"(r[3]) : "r"(a));
}
__device__ __forceinline__ void mma16816(float* c, const unsigned* a, const unsigned* b) {
    asm volatile(
        "mma.sync.aligned.m16n8k16.row.col.f32.f16.f16.f32 "
        "{%0,%1,%2,%3},{%4,%5,%6,%7},{%8,%9},{%0,%1,%2,%3};"
        : "+f"(c[0]), "+f"(c[1]), "+f"(c[2]), "+f"(c[3])
        : "r"(a[0]), "r"(a[1]), "r"(a[2]), "r"(a[3]), "r"(b[0]), "r"(b[1]));
}
__device__ __forceinline__ void cp16(unsigned dst, const void* src) {
    asm volatile("cp.async.cg.shared.global [%0],[%1],16;" :: "r"(dst), "l"(src));
}
#define CP_COMMIT() asm volatile("cp.async.commit_group;")
#define CP_WAIT2()  asm volatile("cp.async.wait_group 2;")
#define CP_WAIT1()  asm volatile("cp.async.wait_group 1;")
#define CP_WAIT0()  asm volatile("cp.async.wait_group 0;")

__device__ __forceinline__ unsigned pack2(float x, float y) {
    __half2 h = __floats2half2_rn(x, y);
    return *reinterpret_cast<unsigned*>(&h);
}
__device__ __forceinline__ float ex2f(float x) {
    float r;
    asm("ex2.approx.ftz.f32 %0, %1;" : "=f"(r) : "f"(x));
    return r;
}
__device__ __forceinline__ unsigned cvth2(float lo, float hi) {
    unsigned d;
    asm("cvt.rn.f16x2.f32 %0, %1, %2;" : "=r"(d) : "f"(hi), "f"(lo));
    return d;
}
__device__ __forceinline__ unsigned ex2h2(unsigned a) {
    unsigned d;
    asm("ex2.approx.f16x2 %0, %1;" : "=r"(d) : "r"(a));
    return d;
}

// ---------------------------------------------------------------------------
// fp32 -> fp16 converts
// ---------------------------------------------------------------------------
__global__ __launch_bounds__(256) void cvt_kernel(
    const float* __restrict__ in, __half* __restrict__ out, int n)
{
    int i = (blockIdx.x * 256 + threadIdx.x) * 4;
    if (i >= n) return;
    float4 v = *(const float4*)(in + i);
    *(unsigned*)(out + i)     = pack2(v.x, v.y);
    *(unsigned*)(out + i + 2) = pack2(v.z, v.w);
}

__global__ __launch_bounds__(256) void cvt_w_kernel(
    const float* __restrict__ W0, const float* __restrict__ W1,
    const float* __restrict__ W2, const float* __restrict__ W3,
    __half* __restrict__ O0, __half* __restrict__ O1,
    __half* __restrict__ O2, __half* __restrict__ O3)
{
    const float* W; __half* O;
    switch (blockIdx.y) {
        case 0: W = W0; O = O0; break;
        case 1: W = W1; O = O1; break;
        case 2: W = W2; O = O2; break;
        default: W = W3; O = O3; break;
    }
    int i = (blockIdx.x * 256 + threadIdx.x) * 4;
    float4 v = *(const float4*)(W + i);
    *(unsigned*)(O + i)     = pack2(v.x, v.y);
    *(unsigned*)(O + i + 2) = pack2(v.z, v.w);
}

// ---------------------------------------------------------------------------
// fp16 mma GEMM. BM=BN=128, BK=64, 3-stage cp.async pipeline, 256 thr
// (8 warps 2x4), warp tile 64x32, dynamic smem 107.5KB (2 CTAs/SM).
// MODE 1: fused QKV (blockIdx.z selects). MODE 0: fp32 row-major out.
// ---------------------------------------------------------------------------
#define GBM 128
#define GBN 128
#define GBK 64
#define ASTR 72
#define BSTR 136
#define A_STAGE (GBM * ASTR)
#define B_STAGE (GBK * BSTR)
#define NSTAGE 3
#define GEMM_SMEM (NSTAGE * (A_STAGE + B_STAGE) * 2)  // 107520 B

template <int MODE>
__global__ __launch_bounds__(256) void gemm_h(
    const __half* __restrict__ Ag,
    const __half* __restrict__ W0g, const __half* __restrict__ W1g,
    const __half* __restrict__ W2g,
    const float* __restrict__ b0, const float* __restrict__ b1,
    const float* __restrict__ b2,
    float* __restrict__ Cf,
    __half* __restrict__ C0, __half* __restrict__ C1, __half* __restrict__ C2)
{
    extern __shared__ __half smem[];
    __half* sA = smem;
    __half* sB = smem + NSTAGE * A_STAGE;

    const __half* Wg; const float* bias; __half* Ch; float scale;
    if (MODE == 1) {
        switch (blockIdx.z) {
            case 0:  Wg = W0g; bias = b0; Ch = C0; scale = QSCALE; break;
            case 1:  Wg = W1g; bias = b1; Ch = C1; scale = 1.0f;   break;
            default: Wg = W2g; bias = b2; Ch = C2; scale = 1.0f;   break;
        }
    } else {
        Wg = W0g; bias = b0; Ch = nullptr; scale = 1.0f;
    }

    const int tid = threadIdx.x;
    const int lane = tid & 31, warp = tid >> 5;
    const int wm = (warp >> 2) * 64;
    const int wn = (warp & 3) * 32;
    const int m0 = blockIdx.y * GBM;
    const int n0 = blockIdx.x * GBN;
    const unsigned sAb = smem_u32(sA), sBb = smem_u32(sB);

    float acc[4][4][4];
    #pragma unroll
    for (int i = 0; i < 4; i++)
        #pragma unroll
        for (int j = 0; j < 4; j++)
            #pragma unroll
            for (int r = 0; r < 4; r++) acc[i][j][r] = 0.0f;

    auto load_stage = [&](int st, int k0) {
        #pragma unroll
        for (int c = 0; c < 4; c++) {
            int id = tid + c * 256;
            int row = id >> 3, col = (id & 7) * 8;
            cp16(sAb + (st * A_STAGE + row * ASTR + col) * 2,
                 Ag + (size_t)(m0 + row) * DM + k0 + col);
        }
        #pragma unroll
        for (int c = 0; c < 4; c++) {
            int id = tid + c * 256;
            int row = id >> 4, col = (id & 15) * 8;
            cp16(sBb + (st * B_STAGE + row * BSTR + col) * 2,
                 Wg + (size_t)(k0 + row) * DM + n0 + col);
        }
    };

    load_stage(0, 0);       CP_COMMIT();
    load_stage(1, GBK);     CP_COMMIT();

    const int NIT = DM / GBK;  // 16
    int cur = 0;
    for (int it = 0; it < NIT; it++) {
        if (it + 2 < NIT) {
            int nst = cur + 2; if (nst >= NSTAGE) nst -= NSTAGE;
            load_stage(nst, (it + 2) * GBK);
            CP_COMMIT();
            CP_WAIT2();
        } else if (it + 1 < NIT) { CP_WAIT1(); }
        else                     { CP_WAIT0(); }
        __syncthreads();

        #pragma unroll
        for (int kk = 0; kk < 4; kk++) {
            unsigned b[4][2];
            #pragma unroll
            for (int nt2 = 0; nt2 < 2; nt2++) {
                unsigned r[4];
                ldsm4t(r, sBb + (cur * B_STAGE + (kk * 16 + (lane & 15)) * BSTR
                                 + wn + nt2 * 16 + ((lane >> 4) & 1) * 8) * 2);
                b[2 * nt2][0] = r[0]; b[2 * nt2][1] = r[1];
                b[2 * nt2 + 1][0] = r[2]; b[2 * nt2 + 1][1] = r[3];
            }
            #pragma unroll
            for (int mt = 0; mt < 4; mt++) {
                unsigned a[4];
                ldsm4(a, sAb + (cur * A_STAGE + (wm + mt * 16 + (lane & 15)) * ASTR
                                + kk * 16 + ((lane >> 4) & 1) * 8) * 2);
                #pragma unroll
                for (int nt = 0; nt < 4; nt++) mma16816(acc[mt][nt], a, b[nt]);
            }
        }
        __syncthreads();
        cur++; if (cur >= NSTAGE) cur -= NSTAGE;
    }

    const int g = lane >> 2, tg = lane & 3;
    #pragma unroll
    for (int mt = 0; mt < 4; mt++) {
        const int r = m0 + wm + mt * 16 + g;
        #pragma unroll
        for (int nt = 0; nt < 4; nt++) {
            const int col = n0 + wn + nt * 8 + 2 * tg;
            const float2 bv = *(const float2*)&bias[col];
            float v00 = (acc[mt][nt][0] + bv.x) * scale;
            float v01 = (acc[mt][nt][1] + bv.y) * scale;
            float v10 = (acc[mt][nt][2] + bv.x) * scale;
            float v11 = (acc[mt][nt][3] + bv.y) * scale;
            if (MODE == 0) {
                *(float2*)&Cf[(size_t)r * DM + col]       = make_float2(v00, v01);
                *(float2*)&Cf[(size_t)(r + 8) * DM + col] = make_float2(v10, v11);
            } else {
                const int h = col >> 6, d = col & 63;
                int bb = r >> 11, ss = r & 2047;
                *(unsigned*)&Ch[(((size_t)(bb * NH + h) * SEQ) + ss) * HD + d] = pack2(v00, v01);
                bb = (r + 8) >> 11; ss = (r + 8) & 2047;
                *(unsigned*)&Ch[(((size_t)(bb * NH + h) * SEQ) + ss) * HD + d] = pack2(v10, v11);
            }
        }
    }
}

// ---------------------------------------------------------------------------
// FlashAttention-2, fp16 mma. 128 thr (4 warps), 32 q rows per warp (two
// 16-row subtiles sharing every K/V ldmatrix fragment). 128 q rows/block.
// NEW: 4-stage KV ring loading 2 tiles ahead -> ONE __syncthreads per
// iteration (the per-iter barrier bounds warp skew, so the stage written
// (it+2)&3 can never collide with the stage read (it&3)).
// ---------------------------------------------------------------------------
#define ATS 64
#define QW  32
#define QBLK 128
#define KSTR 72
#define KV_STAGE (ATS * KSTR)               // halfs per stage per array
#define ATTN_SMEM (8 * KV_STAGE * 2)        // 4 K stages + 4 V stages = 73728 B
#define ONES_H2 0x3C003C00u

__global__ __launch_bounds__(128) void attn_fa(
    const __half* __restrict__ Q, const __half* __restrict__ K,
    const __half* __restrict__ V, __half* __restrict__ Out)
{
    extern __shared__ __half asmem[];
    __half* sK = asmem;                      // stages 0..3
    __half* sV = asmem + 4 * KV_STAGE;       // stages 0..3

    const int bh = blockIdx.y;
    const int q0 = blockIdx.x * QBLK;
    const int tid = threadIdx.x;
    const int warp = tid >> 5, lane = tid & 31;
    const int g = lane >> 2, tg = lane & 3;
    const size_t base = (size_t)bh * SEQ * HD;
    const unsigned sKb = smem_u32(sK), sVb = smem_u32(sV);

    // Q fragments for two 16-row subtiles
    unsigned qf[2][4][4];
    #pragma unroll
    for (int u = 0; u < 2; u++) {
        const int r0 = q0 + warp * QW + u * 16;
        #pragma unroll
        for (int kk = 0; kk < 4; kk++) {
            const size_t i0 = base + (size_t)(r0 + g) * HD + kk * 16 + 2 * tg;
            const size_t i1 = base + (size_t)(r0 + g + 8) * HD + kk * 16 + 2 * tg;
            qf[u][kk][0] = *(const unsigned*)(Q + i0);
            qf[u][kk][1] = *(const unsigned*)(Q + i1);
            qf[u][kk][2] = *(const unsigned*)(Q + i0 + 8);
            qf[u][kk][3] = *(const unsigned*)(Q + i1 + 8);
        }
    }

    auto load_kv = [&](int st, int kv0) {
        #pragma unroll
        for (int c = 0; c < 4; c++) {
            int id = tid + c * 128;
            int row = id >> 3, col = (id & 7) * 8;
            size_t src = base + (size_t)(kv0 + row) * HD + col;
            unsigned off = (st * KV_STAGE + row * KSTR + col) * 2;
            cp16(sKb + off, K + src);
            cp16(sVb + off, V + src);
        }
    };

    float o[2][8][4];
    #pragma unroll
    for (int u = 0; u < 2; u++)
        #pragma unroll
        for (int i = 0; i < 8; i++)
            #pragma unroll
            for (int j = 0; j < 4; j++) o[u][i][j] = 0.0f;
    float lacc[2][4] = {{0.f,0.f,0.f,0.f},{0.f,0.f,0.f,0.f}};
    float m0[2] = {-1e30f, -1e30f}, m1[2] = {-1e30f, -1e30f};
    const unsigned ones[2] = {ONES_H2, ONES_H2};

    const unsigned kladdr = ((lane >> 4) << 3 | (lane & 7)) * KSTR * 2
                            + (((lane >> 3) & 1) * 8) * 2;
    const unsigned vladdr = ((lane & 15)) * KSTR * 2 + (((lane >> 4) & 1) * 8) * 2;

    load_kv(0, 0);      CP_COMMIT();
    load_kv(1, ATS);    CP_COMMIT();

    const int NKV = SEQ / ATS;   // 32
    for (int it = 0; it < NKV; it++) {
        const int st = it & 3;
        if (it + 2 < NKV) { load_kv((it + 2) & 3, (it + 2) * ATS); CP_COMMIT(); CP_WAIT2(); }
        else if (it + 1 < NKV) { CP_WAIT1(); }
        else                   { CP_WAIT0(); }
        __syncthreads();    // publish stage st; also bounds warp skew (<1 iter)

        const unsigned kbase = sKb + st * KV_STAGE * 2;
        const unsigned vbase = sVb + st * KV_STAGE * 2;

        // ---- S = Q @ K^T for both subtiles, sharing each K fragment
        float s[2][8][4];
        #pragma unroll
        for (int u = 0; u < 2; u++)
            #pragma unroll
            for (int i = 0; i < 8; i++)
                #pragma unroll
                for (int j = 0; j < 4; j++) s[u][i][j] = 0.0f;

        #pragma unroll
        for (int kk = 0; kk < 4; kk++) {
            #pragma unroll
            for (int nt2 = 0; nt2 < 4; nt2++) {
                unsigned r[4];
                ldsm4(r, kbase + kladdr + (nt2 * 16 * KSTR + kk * 16) * 2);
                #pragma unroll
                for (int u = 0; u < 2; u++) {
                    mma16816(s[u][2 * nt2],     qf[u][kk], r);
                    mma16816(s[u][2 * nt2 + 1], qf[u][kk], r + 2);
                }
            }
        }

        // ---- softmax per subtile (log2 domain)
        unsigned pa[2][4][4];
        #pragma unroll
        for (int u = 0; u < 2; u++) {
            float mx0 = -1e30f, mx1 = -1e30f;
            #pragma unroll
            for (int nt = 0; nt < 8; nt++) {
                mx0 = fmaxf(mx0, fmaxf(s[u][nt][0], s[u][nt][1]));
                mx1 = fmaxf(mx1, fmaxf(s[u][nt][2], s[u][nt][3]));
            }
            mx0 = fmaxf(mx0, __shfl_xor_sync(~0u, mx0, 1));
            mx0 = fmaxf(mx0, __shfl_xor_sync(~0u, mx0, 2));
            mx1 = fmaxf(mx1, __shfl_xor_sync(~0u, mx1, 1));
            mx1 = fmaxf(mx1, __shfl_xor_sync(~0u, mx1, 2));
            const float mn0 = fmaxf(m0[u], mx0), mn1 = fmaxf(m1[u], mx1);

            const bool nochange = (mn0 == m0[u]) & (mn1 == m1[u]);
            if (!__all_sync(~0u, nochange)) {
                const float c0 = ex2f(m0[u] - mn0), c1 = ex2f(m1[u] - mn1);
                #pragma unroll
                for (int nt = 0; nt < 8; nt++) {
                    o[u][nt][0] *= c0; o[u][nt][1] *= c0;
                    o[u][nt][2] *= c1; o[u][nt][3] *= c1;
                }
                lacc[u][0] *= c0; lacc[u][1] *= c0;
                lacc[u][2] *= c1; lacc[u][3] *= c1;
            }
            m0[u] = mn0; m1[u] = mn1;

            #pragma unroll
            for (int kk = 0; kk < 4; kk++) {
                pa[u][kk][0] = ex2h2(cvth2(s[u][2 * kk][0] - mn0,     s[u][2 * kk][1] - mn0));
                pa[u][kk][1] = ex2h2(cvth2(s[u][2 * kk][2] - mn1,     s[u][2 * kk][3] - mn1));
                pa[u][kk][2] = ex2h2(cvth2(s[u][2 * kk + 1][0] - mn0, s[u][2 * kk + 1][1] - mn0));
                pa[u][kk][3] = ex2h2(cvth2(s[u][2 * kk + 1][2] - mn1, s[u][2 * kk + 1][3] - mn1));
            }
        }

        // ---- O += P @ V ; lacc += P @ ones — sharing each V fragment
        #pragma unroll
        for (int kk = 0; kk < 4; kk++) {
            mma16816(lacc[0], pa[0][kk], ones);
            mma16816(lacc[1], pa[1][kk], ones);
            #pragma unroll
            for (int nt2 = 0; nt2 < 4; nt2++) {
                unsigned r[4];
                ldsm4t(r, vbase + vladdr + (kk * 16 * KSTR + nt2 * 16) * 2);
                #pragma unroll
                for (int u = 0; u < 2; u++) {
                    mma16816(o[u][2 * nt2],     pa[u][kk], r);
                    mma16816(o[u][2 * nt2 + 1], pa[u][kk], r + 2);
                }
            }
        }
        // no trailing barrier: 4-deep ring + per-iter barrier makes the
        // next iteration's write target disjoint from any stage still read
    }

    const int b = bh / NH, h = bh % NH;
    #pragma unroll
    for (int u = 0; u < 2; u++) {
        const float i0 = 1.0f / lacc[u][0], i1 = 1.0f / lacc[u][2];
        const size_t tok = (size_t)b * SEQ + q0 + warp * QW + u * 16 + g;
        #pragma unroll
        for (int nt = 0; nt < 8; nt++) {
            const int col = h * HD + nt * 8 + 2 * tg;
            *(unsigned*)&Out[tok * DM + col]       = pack2(o[u][nt][0] * i0, o[u][nt][1] * i0);
            *(unsigned*)&Out[(tok + 8) * DM + col] = pack2(o[u][nt][2] * i1, o[u][nt][3] * i1);
        }
    }
}

// ---------------------------------------------------------------------------
// Residual + LayerNorm
// ---------------------------------------------------------------------------
__global__ __launch_bounds__(256) void ln_kernel(
    const float* __restrict__ X, const float* __restrict__ P,
    const float* __restrict__ gamma, const float* __restrict__ beta,
    float* __restrict__ out)
{
    const int r = blockIdx.x, t = threadIdx.x;
    const float4 x4 = ((const float4*)(X + (size_t)r * DM))[t];
    const float4 p4 = ((const float4*)(P + (size_t)r * DM))[t];
    float v0 = x4.x + p4.x, v1 = x4.y + p4.y, v2 = x4.z + p4.z, v3 = x4.w + p4.w;

    __shared__ float red[8];
    __shared__ float s_mu, s_rstd;

    float s = v0 + v1 + v2 + v3;
    #pragma unroll
    for (int off = 16; off > 0; off >>= 1) s += __shfl_xor_sync(~0u, s, off);
    if ((t & 31) == 0) red[t >> 5] = s;
    __syncthreads();
    if (t == 0) {
        float tot = 0.f;
        #pragma unroll
        for (int i = 0; i < 8; i++) tot += red[i];
        s_mu = tot * (1.0f / DM);
    }
    __syncthreads();
    const float mu = s_mu;
    float d0 = v0 - mu, d1 = v1 - mu, d2 = v2 - mu, d3 = v3 - mu;
    float sq = d0 * d0 + d1 * d1 + d2 * d2 + d3 * d3;
    #pragma unroll
    for (int off = 16; off > 0; off >>= 1) sq += __shfl_xor_sync(~0u, sq, off);
    if ((t & 31) == 0) red[t >> 5] = sq;
    __syncthreads();
    if (t == 0) {
        float tot = 0.f;
        #pragma unroll
        for (int i = 0; i < 8; i++) tot += red[i];
        s_rstd = rsqrtf(tot * (1.0f / DM) + LN_EPS);
    }
    __syncthreads();
    const float rstd = s_rstd;

    const float4 g4 = ((const float4*)gamma)[t];
    const float4 b4 = ((const float4*)beta)[t];
    float4 o4;
    o4.x = d0 * rstd * g4.x + b4.x;
    o4.y = d1 * rstd * g4.y + b4.y;
    o4.z = d2 * rstd * g4.z + b4.z;
    o4.w = d3 * rstd * g4.w + b4.w;
    ((float4*)(out + (size_t)r * DM))[t] = o4;
}

// ---------------------------------------------------------------------------
// Launch
// ---------------------------------------------------------------------------
extern "C" void kernel_launch(void* const* d_in, const int* in_sizes, int n_in,
                              void* d_out, int out_size)
{
    const float* x     = (const float*)d_in[0];
    const float* Wq    = (const float*)d_in[1];
    const float* bq    = (const float*)d_in[2];
    const float* Wk    = (const float*)d_in[3];
    const float* bk    = (const float*)d_in[4];
    const float* Wv    = (const float*)d_in[5];
    const float* bv    = (const float*)d_in[6];
    const float* Wo    = (const float*)d_in[7];
    const float* bo    = (const float*)d_in[8];
    const float* gamma = (const float*)d_in[9];
    const float* beta  = (const float*)d_in[10];
    float* out = (float*)d_out;

    __half *hx, *hwq, *hwk, *hwv, *hwo, *q, *k, *v, *ah;
    float *proj;
    cudaGetSymbolAddress((void**)&hx,  g_hx);
    cudaGetSymbolAddress((void**)&hwq, g_hwq);
    cudaGetSymbolAddress((void**)&hwk, g_hwk);
    cudaGetSymbolAddress((void**)&hwv, g_hwv);
    cudaGetSymbolAddress((void**)&hwo, g_hwo);
    cudaGetSymbolAddress((void**)&q,   g_q);
    cudaGetSymbolAddress((void**)&k,   g_k);
    cudaGetSymbolAddress((void**)&v,   g_v);
    cudaGetSymbolAddress((void**)&ah,  g_ah);
    cudaGetSymbolAddress((void**)&proj, g_proj);

    cudaFuncSetAttribute(gemm_h<0>, cudaFuncAttributeMaxDynamicSharedMemorySize, GEMM_SMEM);
    cudaFuncSetAttribute(gemm_h<1>, cudaFuncAttributeMaxDynamicSharedMemorySize, GEMM_SMEM);
    cudaFuncSetAttribute(attn_fa,   cudaFuncAttributeMaxDynamicSharedMemorySize, ATTN_SMEM);

    cvt_kernel<<<NTOK * DM / 1024, 256>>>(x, hx, NTOK * DM);
    cvt_w_kernel<<<dim3(DM * DM / 1024, 4), 256>>>(Wq, Wk, Wv, Wo,
                                                   hwq, hwk, hwv, hwo);

    gemm_h<1><<<dim3(DM / GBN, NTOK / GBM, 3), 256, GEMM_SMEM>>>(
        hx, hwq, hwk, hwv, bq, bk, bv, nullptr, q, k, v);

    attn_fa<<<dim3(SEQ / QBLK, BATCH * NH), 128, ATTN_SMEM>>>(q, k, v, ah);

    gemm_h<0><<<dim3(DM / GBN, NTOK / GBM, 1), 256, GEMM_SMEM>>>(
        ah, hwo, nullptr, nullptr, bo, nullptr, nullptr, proj,
        nullptr, nullptr, nullptr);

    ln_kernel<<<NTOK, 256>>>(x, proj, gamma, beta, out);
}